// round 1
// baseline (speedup 1.0000x reference)
#include <cuda_runtime.h>
#include <math.h>

// ---------------- problem constants ----------------
#define BB   4
#define SS   1024
#define DD   768
#define LL   12
#define HH   12
#define HS   64
#define VV   32000
#define MR   (BB*SS)        // 4096 rows
#define D3   (3*DD)         // 2304 (qkv concat)
#define F1N  (4*DD)         // 3072
#define F2N  (3*DD)         // 2304

// ---------------- scratch (static device allocs) ----------------
__device__ float g_x   [MR*DD];
__device__ float g_h   [MR*DD];
__device__ float g_qkv [MR*D3];
__device__ float g_att [(size_t)BB*HH*SS*SS];   // 201 MB
__device__ float g_o   [MR*DD];
__device__ float g_f1  [MR*F1N];
__device__ float g_f2  [MR*F2N];
__device__ float g_wt  [(size_t)LL*DD*D3];      // repacked qkv weights
__device__ float g_bqkv[LL*D3];
__device__ float g_rowloss[MR];

// ---------------- block reductions (deterministic) ----------------
__device__ __forceinline__ float blockSum256(float v, float* sm) {
    #pragma unroll
    for (int o = 16; o > 0; o >>= 1) v += __shfl_down_sync(0xffffffffu, v, o);
    int lane = threadIdx.x & 31, w = threadIdx.x >> 5;
    if (lane == 0) sm[w] = v;
    __syncthreads();
    if (threadIdx.x < 32) {
        v = (lane < 8) ? sm[lane] : 0.0f;
        #pragma unroll
        for (int o = 4; o > 0; o >>= 1) v += __shfl_down_sync(0xffffffffu, v, o);
        if (lane == 0) sm[0] = v;
    }
    __syncthreads();
    float r = sm[0];
    __syncthreads();
    return r;
}

__device__ __forceinline__ float blockMax256(float v, float* sm) {
    #pragma unroll
    for (int o = 16; o > 0; o >>= 1) v = fmaxf(v, __shfl_down_sync(0xffffffffu, v, o));
    int lane = threadIdx.x & 31, w = threadIdx.x >> 5;
    if (lane == 0) sm[w] = v;
    __syncthreads();
    if (threadIdx.x < 32) {
        v = (lane < 8) ? sm[lane] : -1e30f;
        #pragma unroll
        for (int o = 4; o > 0; o >>= 1) v = fmaxf(v, __shfl_down_sync(0xffffffffu, v, o));
        if (lane == 0) sm[0] = v;
    }
    __syncthreads();
    float r = sm[0];
    __syncthreads();
    return r;
}

// ---------------- prep: repack qkv weights & biases ----------------
__global__ void __launch_bounds__(256) prep_w_k(const float* __restrict__ Wq,
                                                const float* __restrict__ Wk,
                                                const float* __restrict__ Wv) {
    size_t total = (size_t)LL * DD * D3;
    for (size_t i = (size_t)blockIdx.x * 256 + threadIdx.x; i < total;
         i += (size_t)gridDim.x * 256) {
        int n = (int)(i % D3);
        size_t r = i / D3;
        int d = (int)(r % DD);
        int l = (int)(r / DD);
        int which = n / DD;
        int h = (n % DD) / HS;
        int e = n % HS;
        const float* W = (which == 0) ? Wq : ((which == 1) ? Wk : Wv);
        g_wt[i] = W[(((size_t)l * HH + h) * DD + d) * HS + e];
    }
}

__global__ void __launch_bounds__(256) prep_b_k(const float* __restrict__ bq,
                                                const float* __restrict__ bk,
                                                const float* __restrict__ bv) {
    int i = blockIdx.x * 256 + threadIdx.x;
    if (i >= LL * D3) return;
    int l = i / D3, n = i % D3;
    int which = n / DD;
    int h = (n % DD) / HS;
    int e = n % HS;
    const float* b = (which == 0) ? bq : ((which == 1) ? bk : bv);
    g_bqkv[i] = b[(l * HH + h) * HS + e];
}

// ---------------- embedding ----------------
__global__ void __launch_bounds__(256) embed_k(const int* __restrict__ idx,
                                               const float* __restrict__ tok,
                                               const float* __restrict__ pos) {
    int i = blockIdx.x * 256 + threadIdx.x;
    if (i >= MR * DD) return;
    int m = i / DD, d = i % DD;
    int s = m % SS;
    // pos_emb / sqrt(D)
    g_x[i] = tok[(size_t)idx[m] * DD + d] + pos[s * DD + d] * 0.03608439182435161f;
}

// ---------------- layernorm ----------------
__global__ void __launch_bounds__(256) ln_k(const float* __restrict__ x,
                                            float* __restrict__ out,
                                            const float* __restrict__ g,
                                            const float* __restrict__ b) {
    __shared__ float sm[8];
    int r = blockIdx.x, t = threadIdx.x;
    const float* xr = x + (size_t)r * DD;
    float v0 = xr[t], v1 = xr[t + 256], v2 = xr[t + 512];
    float mu = blockSum256(v0 + v1 + v2, sm) * (1.0f / (float)DD);
    float d0 = v0 - mu, d1 = v1 - mu, d2 = v2 - mu;
    float var = blockSum256(d0 * d0 + d1 * d1 + d2 * d2, sm) * (1.0f / (float)DD);
    float rs = rsqrtf(var + 1e-5f);
    float* orow = out + (size_t)r * DD;
    orow[t]       = d0 * rs * g[t]       + b[t];
    orow[t + 256] = d1 * rs * g[t + 256] + b[t + 256];
    orow[t + 512] = d2 * rs * g[t + 512] + b[t + 512];
}

// ---------------- generic SGEMM: C = epilogue(A[MxK] @ B[KxN] + bias) ----------------
// mode 0: +bias      mode 1: resid + scale*(..+bias)     mode 2: gelu(..+bias)
__global__ void __launch_bounds__(256) gemm128(const float* __restrict__ A,
                                               const float* __restrict__ B,
                                               const float* __restrict__ bias,
                                               const float* __restrict__ resid,
                                               const float* __restrict__ scale_ptr,
                                               float* __restrict__ C,
                                               int M, int N, int K, int mode) {
    __shared__ float As[16][128];
    __shared__ float Bs[16][128];
    int m0 = blockIdx.y * 128, n0 = blockIdx.x * 128;
    int t = threadIdx.x, tx = t & 15, ty = t >> 4;
    float acc[8][8];
    #pragma unroll
    for (int i = 0; i < 8; i++)
        #pragma unroll
        for (int j = 0; j < 8; j++) acc[i][j] = 0.0f;

    for (int k0 = 0; k0 < K; k0 += 16) {
        // A tile 128x16 -> As[k][m]
        {
            int row = t >> 1;
            int cb = (t & 1) * 8;
            const float* ap = A + (size_t)(m0 + row) * K + k0 + cb;
            float4 a0 = *(const float4*)(ap);
            float4 a1 = *(const float4*)(ap + 4);
            As[cb + 0][row] = a0.x; As[cb + 1][row] = a0.y;
            As[cb + 2][row] = a0.z; As[cb + 3][row] = a0.w;
            As[cb + 4][row] = a1.x; As[cb + 5][row] = a1.y;
            As[cb + 6][row] = a1.z; As[cb + 7][row] = a1.w;
        }
        // B tile 16x128 -> Bs[k][n]
        {
            int krow = t >> 5;
            int c4 = (t & 31) * 4;
            *(float4*)&Bs[krow][c4]     = *(const float4*)(B + (size_t)(k0 + krow) * N + n0 + c4);
            *(float4*)&Bs[krow + 8][c4] = *(const float4*)(B + (size_t)(k0 + krow + 8) * N + n0 + c4);
        }
        __syncthreads();
        #pragma unroll
        for (int kk = 0; kk < 16; kk++) {
            float a[8], bb[8];
            *(float4*)&a[0]  = *(const float4*)&As[kk][ty * 8];
            *(float4*)&a[4]  = *(const float4*)&As[kk][ty * 8 + 4];
            *(float4*)&bb[0] = *(const float4*)&Bs[kk][tx * 8];
            *(float4*)&bb[4] = *(const float4*)&Bs[kk][tx * 8 + 4];
            #pragma unroll
            for (int i = 0; i < 8; i++)
                #pragma unroll
                for (int j = 0; j < 8; j++) acc[i][j] = fmaf(a[i], bb[j], acc[i][j]);
        }
        __syncthreads();
    }

    float scale = 1.0f;
    if (scale_ptr) scale = *scale_ptr;
    #pragma unroll
    for (int i = 0; i < 8; i++) {
        int gm = m0 + ty * 8 + i;
        size_t ro = (size_t)gm * N;
        #pragma unroll
        for (int j = 0; j < 8; j++) {
            int gn = n0 + tx * 8 + j;
            float v = acc[i][j];
            if (bias) v += bias[gn];
            if (mode == 1)      v = resid[ro + gn] + scale * v;
            else if (mode == 2) v = 0.5f * v * (1.0f + erff(v * 0.7071067811865476f));
            C[ro + gn] = v;
        }
    }
}

// ---------------- lm_head: C = A[MxK] @ Bt[NxK]^T ----------------
__global__ void __launch_bounds__(256) gemm_nt(const float* __restrict__ A,
                                               const float* __restrict__ Bt,
                                               float* __restrict__ C,
                                               int M, int N, int K) {
    __shared__ float As[16][128];
    __shared__ float Bs[16][128];
    int m0 = blockIdx.y * 128, n0 = blockIdx.x * 128;
    int t = threadIdx.x, tx = t & 15, ty = t >> 4;
    float acc[8][8];
    #pragma unroll
    for (int i = 0; i < 8; i++)
        #pragma unroll
        for (int j = 0; j < 8; j++) acc[i][j] = 0.0f;

    for (int k0 = 0; k0 < K; k0 += 16) {
        int row = t >> 1;
        int cb = (t & 1) * 8;
        {
            const float* ap = A + (size_t)(m0 + row) * K + k0 + cb;
            float4 a0 = *(const float4*)(ap);
            float4 a1 = *(const float4*)(ap + 4);
            As[cb + 0][row] = a0.x; As[cb + 1][row] = a0.y;
            As[cb + 2][row] = a0.z; As[cb + 3][row] = a0.w;
            As[cb + 4][row] = a1.x; As[cb + 5][row] = a1.y;
            As[cb + 6][row] = a1.z; As[cb + 7][row] = a1.w;
        }
        {
            const float* bp = Bt + (size_t)(n0 + row) * K + k0 + cb;
            float4 b0 = *(const float4*)(bp);
            float4 b1 = *(const float4*)(bp + 4);
            Bs[cb + 0][row] = b0.x; Bs[cb + 1][row] = b0.y;
            Bs[cb + 2][row] = b0.z; Bs[cb + 3][row] = b0.w;
            Bs[cb + 4][row] = b1.x; Bs[cb + 5][row] = b1.y;
            Bs[cb + 6][row] = b1.z; Bs[cb + 7][row] = b1.w;
        }
        __syncthreads();
        #pragma unroll
        for (int kk = 0; kk < 16; kk++) {
            float a[8], bb[8];
            *(float4*)&a[0]  = *(const float4*)&As[kk][ty * 8];
            *(float4*)&a[4]  = *(const float4*)&As[kk][ty * 8 + 4];
            *(float4*)&bb[0] = *(const float4*)&Bs[kk][tx * 8];
            *(float4*)&bb[4] = *(const float4*)&Bs[kk][tx * 8 + 4];
            #pragma unroll
            for (int i = 0; i < 8; i++)
                #pragma unroll
                for (int j = 0; j < 8; j++) acc[i][j] = fmaf(a[i], bb[j], acc[i][j]);
        }
        __syncthreads();
    }
    #pragma unroll
    for (int i = 0; i < 8; i++) {
        size_t ro = (size_t)(m0 + ty * 8 + i) * N;
        #pragma unroll
        for (int j = 0; j < 8; j++)
            C[ro + n0 + tx * 8 + j] = acc[i][j];
    }
}

// ---------------- attention scores (causal tile skip) ----------------
__global__ void __launch_bounds__(256) scores_k() {
    int bh = blockIdx.z, b = bh / HH, h = bh % HH;
    int s0 = blockIdx.y * 64, t0 = blockIdx.x * 64;
    if (t0 > s0 + 63) return;                 // fully masked tile
    __shared__ float Qs[64][72], Ks[64][72];
    const float* base = g_qkv + (size_t)b * SS * D3 + h * HS;
    int t = threadIdx.x;
    #pragma unroll
    for (int i = 0; i < 4; i++) {
        int idx4 = t + i * 256;
        int row = idx4 >> 4, c4 = (idx4 & 15) * 4;
        *(float4*)&Qs[row][c4] = *(const float4*)(base + (size_t)(s0 + row) * D3 + c4);
        *(float4*)&Ks[row][c4] = *(const float4*)(base + DD + (size_t)(t0 + row) * D3 + c4);
    }
    __syncthreads();
    int tx = t & 15, ty = t >> 4;
    float acc[4][4] = {};
    #pragma unroll
    for (int kk = 0; kk < 64; kk++) {
        float a[4], bb[4];
        #pragma unroll
        for (int i = 0; i < 4; i++) a[i]  = Qs[ty * 4 + i][kk];
        #pragma unroll
        for (int j = 0; j < 4; j++) bb[j] = Ks[tx * 4 + j][kk];
        #pragma unroll
        for (int i = 0; i < 4; i++)
            #pragma unroll
            for (int j = 0; j < 4; j++) acc[i][j] = fmaf(a[i], bb[j], acc[i][j]);
    }
    size_t ob = (size_t)bh * SS * SS;
    #pragma unroll
    for (int i = 0; i < 4; i++)
        #pragma unroll
        for (int j = 0; j < 4; j++)
            g_att[ob + (size_t)(s0 + ty * 4 + i) * SS + t0 + tx * 4 + j] = acc[i][j] * 0.125f;
}

// ---------------- causal softmax (in place on g_att) ----------------
__global__ void __launch_bounds__(256) softmax_k() {
    __shared__ float sm[8];
    int row = blockIdx.x;            // bh*S + s
    int s = row % SS;
    float* p = g_att + (size_t)(row / SS) * SS * SS + (size_t)s * SS;
    int n = s + 1, t = threadIdx.x;
    float mx = -1e30f;
    for (int i = t; i < n; i += 256) mx = fmaxf(mx, p[i]);
    mx = blockMax256(mx, sm);
    float sum = 0.0f;
    for (int i = t; i < n; i += 256) sum += expf(p[i] - mx);
    sum = blockSum256(sum, sm);
    float inv = 1.0f / sum;
    for (int i = t; i < n; i += 256) p[i] = expf(p[i] - mx) * inv;
    for (int i = n + t; i < SS; i += 256) p[i] = 0.0f;
}

// ---------------- AV: o = att @ v ----------------
__global__ void __launch_bounds__(256) av_k() {
    int bh = blockIdx.y, b = bh / HH, h = bh % HH;
    int s0 = blockIdx.x * 64;
    __shared__ float Ps[64][72], Vs[64][72];
    int t = threadIdx.x, tx = t & 15, ty = t >> 4;
    float acc[4][4] = {};
    const float* vbase = g_qkv + (size_t)b * SS * D3 + 2 * DD + h * HS;
    size_t ab = (size_t)bh * SS * SS;
    for (int k0 = 0; k0 <= s0 + 63; k0 += 64) {
        #pragma unroll
        for (int i = 0; i < 4; i++) {
            int idx4 = t + i * 256;
            int row = idx4 >> 4, c4 = (idx4 & 15) * 4;
            *(float4*)&Ps[row][c4] = *(const float4*)(g_att + ab + (size_t)(s0 + row) * SS + k0 + c4);
            *(float4*)&Vs[row][c4] = *(const float4*)(vbase + (size_t)(k0 + row) * D3 + c4);
        }
        __syncthreads();
        #pragma unroll
        for (int kk = 0; kk < 64; kk++) {
            float a[4], bb[4];
            #pragma unroll
            for (int i = 0; i < 4; i++) a[i] = Ps[ty * 4 + i][kk];
            *(float4*)&bb[0] = *(const float4*)&Vs[kk][tx * 4];
            #pragma unroll
            for (int i = 0; i < 4; i++)
                #pragma unroll
                for (int j = 0; j < 4; j++) acc[i][j] = fmaf(a[i], bb[j], acc[i][j]);
        }
        __syncthreads();
    }
    #pragma unroll
    for (int i = 0; i < 4; i++)
        #pragma unroll
        for (int j = 0; j < 4; j++)
            g_o[(size_t)(b * SS + s0 + ty * 4 + i) * DD + h * HS + tx * 4 + j] = acc[i][j];
}

// ---------------- loss ----------------
__global__ void __launch_bounds__(256) rowloss_k(const float* __restrict__ logits,
                                                 const int* __restrict__ targets) {
    __shared__ float sm[8];
    int m = blockIdx.x, t = threadIdx.x;
    const float* p = logits + (size_t)m * VV;
    float mx = -1e30f;
    for (int i = t; i < VV; i += 256) mx = fmaxf(mx, p[i]);
    mx = blockMax256(mx, sm);
    float sum = 0.0f;
    for (int i = t; i < VV; i += 256) sum += expf(p[i] - mx);
    sum = blockSum256(sum, sm);
    if (t == 0) {
        float lt = p[targets[m]];
        g_rowloss[m] = -(lt - mx - logf(sum));
    }
}

__global__ void __launch_bounds__(256) lossreduce_k(float* __restrict__ out) {
    __shared__ float sm[8];
    float s = 0.0f;
    for (int i = threadIdx.x; i < MR; i += 256) s += g_rowloss[i];
    s = blockSum256(s, sm);
    if (threadIdx.x == 0) out[0] = s / (float)MR;
}

// ---------------- launch ----------------
extern "C" void kernel_launch(void* const* d_in, const int* in_sizes, int n_in,
                              void* d_out, int out_size) {
    const int*   idx     = (const int*)  d_in[0];
    const int*   targets = (const int*)  d_in[1];
    const float* tok     = (const float*)d_in[2];
    const float* pos     = (const float*)d_in[3];
    const float* Wq      = (const float*)d_in[4];
    const float* bq      = (const float*)d_in[5];
    const float* Wk      = (const float*)d_in[6];
    const float* bk      = (const float*)d_in[7];
    const float* Wv      = (const float*)d_in[8];
    const float* bv      = (const float*)d_in[9];
    const float* Wo      = (const float*)d_in[10];
    const float* bo      = (const float*)d_in[11];
    const float* ln1g    = (const float*)d_in[12];
    const float* ln1b    = (const float*)d_in[13];
    const float* ln2g    = (const float*)d_in[14];
    const float* ln2b    = (const float*)d_in[15];
    const float* W1      = (const float*)d_in[16];
    const float* b1      = (const float*)d_in[17];
    const float* W2      = (const float*)d_in[18];
    const float* b2      = (const float*)d_in[19];
    const float* W3      = (const float*)d_in[20];
    const float* b3      = (const float*)d_in[21];
    const float* att_sc  = (const float*)d_in[22];
    const float* ffd_sc  = (const float*)d_in[23];
    const float* lnfg    = (const float*)d_in[24];
    const float* lnfb    = (const float*)d_in[25];
    float* out = (float*)d_out;

    float *px, *ph, *pqkv, *po, *pf1, *pf2, *pwt, *pbq;
    cudaGetSymbolAddress((void**)&px,   g_x);
    cudaGetSymbolAddress((void**)&ph,   g_h);
    cudaGetSymbolAddress((void**)&pqkv, g_qkv);
    cudaGetSymbolAddress((void**)&po,   g_o);
    cudaGetSymbolAddress((void**)&pf1,  g_f1);
    cudaGetSymbolAddress((void**)&pf2,  g_f2);
    cudaGetSymbolAddress((void**)&pwt,  g_wt);
    cudaGetSymbolAddress((void**)&pbq,  g_bqkv);

    prep_w_k<<<4096, 256>>>(Wq, Wk, Wv);
    prep_b_k<<<(LL * D3 + 255) / 256, 256>>>(bq, bk, bv);
    embed_k<<<(MR * DD + 255) / 256, 256>>>(idx, tok, pos);

    for (int l = 0; l < LL; l++) {
        ln_k<<<MR, 256>>>(px, ph, ln1g + l * DD, ln1b + l * DD);
        // QKV: [4096,768] @ [768,2304]
        gemm128<<<dim3(D3 / 128, MR / 128), 256>>>(
            ph, pwt + (size_t)l * DD * D3, pbq + l * D3,
            nullptr, nullptr, pqkv, MR, D3, DD, 0);
        scores_k<<<dim3(SS / 64, SS / 64, BB * HH), 256>>>();
        softmax_k<<<BB * HH * SS, 256>>>();
        av_k<<<dim3(SS / 64, BB * HH), 256>>>();
        // x += att_scale * (o @ Wo + bo)
        gemm128<<<dim3(DD / 128, MR / 128), 256>>>(
            po, Wo + (size_t)l * DD * DD, bo + l * DD,
            px, att_sc + l, px, MR, DD, DD, 1);
        ln_k<<<MR, 256>>>(px, ph, ln2g + l * DD, ln2b + l * DD);
        gemm128<<<dim3(F1N / 128, MR / 128), 256>>>(
            ph, W1 + (size_t)l * DD * F1N, b1 + l * F1N,
            nullptr, nullptr, pf1, MR, F1N, DD, 2);
        gemm128<<<dim3(F2N / 128, MR / 128), 256>>>(
            pf1, W2 + (size_t)l * F1N * F2N, b2 + l * F2N,
            nullptr, nullptr, pf2, MR, F2N, F1N, 2);
        gemm128<<<dim3(DD / 128, MR / 128), 256>>>(
            pf2, W3 + (size_t)l * F2N * DD, b3 + l * DD,
            px, ffd_sc + l, px, MR, DD, F2N, 1);
    }

    ln_k<<<MR, 256>>>(px, ph, lnfg, lnfb);
    gemm_nt<<<dim3(VV / 128, MR / 128), 256>>>(ph, tok, out, MR, VV, DD);
    rowloss_k<<<MR, 256>>>(out, targets);
    if ((long long)out_size > (long long)MR * VV)
        lossreduce_k<<<1, 256>>>(out + (size_t)MR * VV);
}

// round 6
// speedup vs baseline: 2.0389x; 2.0389x over previous
#include <cuda_runtime.h>
#include <cuda_bf16.h>
#include <stdint.h>
#include <stddef.h>
#include <math.h>

// ---------------- problem constants ----------------
#define BB   4
#define SS   1024
#define DD   768
#define LL   12
#define HH   12
#define HS   64
#define VV   32000
#define MR   (BB*SS)        // 4096 rows
#define D3   (3*DD)         // 2304 (qkv concat)
#define F1N  (4*DD)         // 3072
#define F2N  (3*DD)         // 2304

// ---------------- scratch (static device allocs) ----------------
__device__ float g_x   [MR*DD];                 // residual stream fp32
__device__ __nv_bfloat16 g_ah[MR*DD];           // ln output split hi
__device__ __nv_bfloat16 g_al[MR*DD];           // ln output split lo
__device__ float g_qkv [MR*D3];
__device__ float g_att [(size_t)BB*HH*SS*SS];   // 201 MB
__device__ __nv_bfloat16 g_oh[MR*DD];
__device__ __nv_bfloat16 g_ol[MR*DD];
__device__ __nv_bfloat16 g_f1h[(size_t)MR*F1N];
__device__ __nv_bfloat16 g_f1l[(size_t)MR*F1N];
__device__ __nv_bfloat16 g_f2h[(size_t)MR*F2N];
__device__ __nv_bfloat16 g_f2l[(size_t)MR*F2N];
// weights, transposed to [N,K], split bf16 hi/lo
__device__ __nv_bfloat16 g_wqkvh[(size_t)LL*D3*DD];
__device__ __nv_bfloat16 g_wqkvl[(size_t)LL*D3*DD];
__device__ __nv_bfloat16 g_woh[(size_t)LL*DD*DD];
__device__ __nv_bfloat16 g_wol[(size_t)LL*DD*DD];
__device__ __nv_bfloat16 g_w1h[(size_t)LL*F1N*DD];
__device__ __nv_bfloat16 g_w1l[(size_t)LL*F1N*DD];
__device__ __nv_bfloat16 g_w2h[(size_t)LL*F2N*F1N];
__device__ __nv_bfloat16 g_w2l[(size_t)LL*F2N*F1N];
__device__ __nv_bfloat16 g_w3h[(size_t)LL*DD*F2N];
__device__ __nv_bfloat16 g_w3l[(size_t)LL*DD*F2N];
__device__ __nv_bfloat16 g_wvh[(size_t)VV*DD];   // tok_emb (already [N,K])
__device__ __nv_bfloat16 g_wvl[(size_t)VV*DD];
__device__ float g_bqkv[LL*D3];
__device__ float g_rowloss[MR];

// ================= PTX helpers (sm_100 base target safe) =================
__device__ __forceinline__ uint32_t smem_u32(const void* p) {
    uint32_t a;
    asm("{ .reg .u64 t; cvta.to.shared.u64 t, %1; cvt.u32.u64 %0, t; }" : "=r"(a) : "l"(p));
    return a;
}
__device__ __forceinline__ uint32_t lds32(uint32_t a) {
    uint32_t v;
    asm volatile("ld.shared.b32 %0, [%1];" : "=r"(v) : "r"(a));
    return v;
}
__device__ __forceinline__ void cp16(uint32_t d, const void* s) {
    asm volatile("cp.async.cg.shared.global [%0], [%1], 16;" :: "r"(d), "l"(s));
}
#define CP_COMMIT() asm volatile("cp.async.commit_group;" ::: "memory")
#define CP_WAIT(n)  asm volatile("cp.async.wait_group %0;" :: "n"(n) : "memory")

// D = A(16x16 row) * B(16x8 col) + D, bf16 in, fp32 out
__device__ __forceinline__ void mma16816(float* c, const uint32_t* a, uint32_t b0, uint32_t b1) {
    asm volatile(
        "mma.sync.aligned.m16n8k16.row.col.f32.bf16.bf16.f32 "
        "{%0,%1,%2,%3}, {%4,%5,%6,%7}, {%8,%9}, {%0,%1,%2,%3};"
        : "+f"(c[0]), "+f"(c[1]), "+f"(c[2]), "+f"(c[3])
        : "r"(a[0]), "r"(a[1]), "r"(a[2]), "r"(a[3]), "r"(b0), "r"(b1));
}

// ---------------- block reductions (deterministic) ----------------
__device__ __forceinline__ float blockSum256(float v, float* sm) {
    #pragma unroll
    for (int o = 16; o > 0; o >>= 1) v += __shfl_down_sync(0xffffffffu, v, o);
    int lane = threadIdx.x & 31, w = threadIdx.x >> 5;
    if (lane == 0) sm[w] = v;
    __syncthreads();
    if (threadIdx.x < 32) {
        v = (lane < 8) ? sm[lane] : 0.0f;
        #pragma unroll
        for (int o = 4; o > 0; o >>= 1) v += __shfl_down_sync(0xffffffffu, v, o);
        if (lane == 0) sm[0] = v;
    }
    __syncthreads();
    float r = sm[0];
    __syncthreads();
    return r;
}
__device__ __forceinline__ float blockMax256(float v, float* sm) {
    #pragma unroll
    for (int o = 16; o > 0; o >>= 1) v = fmaxf(v, __shfl_down_sync(0xffffffffu, v, o));
    int lane = threadIdx.x & 31, w = threadIdx.x >> 5;
    if (lane == 0) sm[w] = v;
    __syncthreads();
    if (threadIdx.x < 32) {
        v = (lane < 8) ? sm[lane] : -1e30f;
        #pragma unroll
        for (int o = 4; o > 0; o >>= 1) v = fmaxf(v, __shfl_down_sync(0xffffffffu, v, o));
        if (lane == 0) sm[0] = v;
    }
    __syncthreads();
    float r = sm[0];
    __syncthreads();
    return r;
}

// ---------------- weight prep: tiled transpose + bf16 split ----------------
__global__ void __launch_bounds__(256) tsplit_k(const float* __restrict__ src,
                                                __nv_bfloat16* __restrict__ dh,
                                                __nv_bfloat16* __restrict__ dl,
                                                int K, int N) {
    __shared__ float tile[32][33];
    int k0 = blockIdx.x * 32, n0 = blockIdx.y * 32;
    size_t so = (size_t)blockIdx.z * K * N;
    int tx = threadIdx.x, ty = threadIdx.y;   // (32,8)
    #pragma unroll
    for (int r = 0; r < 32; r += 8)
        tile[ty + r][tx] = src[so + (size_t)(k0 + ty + r) * N + n0 + tx];
    __syncthreads();
    #pragma unroll
    for (int r = 0; r < 32; r += 8) {
        float v = tile[tx][ty + r];
        size_t di = so + (size_t)(n0 + ty + r) * K + k0 + tx;
        __nv_bfloat16 h = __float2bfloat16(v);
        dh[di] = h;
        dl[di] = __float2bfloat16(v - __bfloat162float(h));
    }
}

// qkv: src [L*HH][DD][HS]; dst row n = nbase + h*HS + e, col k = d
__global__ void __launch_bounds__(256) tsplit_qkv_k(const float* __restrict__ src,
                                                    __nv_bfloat16* __restrict__ dh,
                                                    __nv_bfloat16* __restrict__ dl,
                                                    int nbase) {
    __shared__ float tile[32][33];
    int l = blockIdx.z / HH, h = blockIdx.z % HH;
    int k0 = blockIdx.x * 32, n0 = blockIdx.y * 32;
    const float* s = src + (size_t)blockIdx.z * DD * HS;
    size_t dbase = (size_t)l * D3 * DD + (size_t)(nbase + h * HS) * DD;
    int tx = threadIdx.x, ty = threadIdx.y;
    #pragma unroll
    for (int r = 0; r < 32; r += 8)
        tile[ty + r][tx] = s[(size_t)(k0 + ty + r) * HS + n0 + tx];
    __syncthreads();
    #pragma unroll
    for (int r = 0; r < 32; r += 8) {
        float v = tile[tx][ty + r];
        size_t di = dbase + (size_t)(n0 + ty + r) * DD + k0 + tx;
        __nv_bfloat16 hi = __float2bfloat16(v);
        dh[di] = hi;
        dl[di] = __float2bfloat16(v - __bfloat162float(hi));
    }
}

__global__ void __launch_bounds__(256) split_k(const float* __restrict__ src,
                                               __nv_bfloat16* __restrict__ dh,
                                               __nv_bfloat16* __restrict__ dl, int n) {
    int i = blockIdx.x * 256 + threadIdx.x;
    if (i >= n) return;
    float v = src[i];
    __nv_bfloat16 h = __float2bfloat16(v);
    dh[i] = h;
    dl[i] = __float2bfloat16(v - __bfloat162float(h));
}

__global__ void __launch_bounds__(256) prep_b_k(const float* __restrict__ bq,
                                                const float* __restrict__ bk,
                                                const float* __restrict__ bv) {
    int i = blockIdx.x * 256 + threadIdx.x;
    if (i >= LL * D3) return;
    int l = i / D3, n = i % D3;
    int which = n / DD;
    int h = (n % DD) / HS;
    int e = n % HS;
    const float* b = (which == 0) ? bq : ((which == 1) ? bk : bv);
    g_bqkv[i] = b[(l * HH + h) * HS + e];
}

// ---------------- embedding ----------------
__global__ void __launch_bounds__(256) embed_k(const int* __restrict__ idx,
                                               const float* __restrict__ tok,
                                               const float* __restrict__ pos) {
    int i = blockIdx.x * 256 + threadIdx.x;
    if (i >= MR * DD) return;
    int m = i / DD, d = i % DD;
    int s = m % SS;
    g_x[i] = tok[(size_t)idx[m] * DD + d] + pos[s * DD + d] * 0.03608439182435161f;
}

// ---------------- layernorm -> split bf16 ----------------
__global__ void __launch_bounds__(256) ln_k(const float* __restrict__ x,
                                            const float* __restrict__ g,
                                            const float* __restrict__ b,
                                            __nv_bfloat16* __restrict__ oh,
                                            __nv_bfloat16* __restrict__ ol) {
    __shared__ float sm[8];
    int r = blockIdx.x, t = threadIdx.x;
    const float* xr = x + (size_t)r * DD;
    float v0 = xr[t], v1 = xr[t + 256], v2 = xr[t + 512];
    float mu = blockSum256(v0 + v1 + v2, sm) * (1.0f / (float)DD);
    float d0 = v0 - mu, d1 = v1 - mu, d2 = v2 - mu;
    float var = blockSum256(d0 * d0 + d1 * d1 + d2 * d2, sm) * (1.0f / (float)DD);
    float rs = rsqrtf(var + 1e-5f);
    size_t ro = (size_t)r * DD;
    #pragma unroll
    for (int p = 0; p < 3; p++) {
        int c = t + p * 256;
        float dv = (p == 0 ? d0 : (p == 1 ? d1 : d2));
        float v = dv * rs * g[c] + b[c];
        __nv_bfloat16 h = __float2bfloat16(v);
        oh[ro + c] = h;
        ol[ro + c] = __float2bfloat16(v - __bfloat162float(h));
    }
}

// ---------------- mma.sync split-bf16 GEMM ----------------
// C[M,N] = epi(Ah@Bh^T + Ah@Bl^T + Al@Bh^T + bias)
// A: [M,K] bf16 row-major; B: [N,K] bf16 row-major.
// CTA tile 128x128, K=16 per stage, double-buffered cp.async.
// Static smem: 2 stages x 4 tiles x 128 rows x 48 B = 49152 B (<= 48KB static).
// Row pad to 48 B: fragment loads conflict-free ((g*12+t4) mod 32 all distinct).
// 8 warps, each 32(M) x 64(N).
// mode 0: +bias -> outf ; mode 1: resid + scale*(..+bias) -> outf ;
// mode 2: gelu(..+bias) -> outh/outl (split bf16)
#define ROWB   48
#define TILE_B (128*ROWB)     // 6144
#define STG_B  (4*TILE_B)     // 24576

__device__ __forceinline__ void load_stage16(uint32_t base,
                                             const __nv_bfloat16* __restrict__ Ah,
                                             const __nv_bfloat16* __restrict__ Al,
                                             const __nv_bfloat16* __restrict__ Bh,
                                             const __nv_bfloat16* __restrict__ Bl,
                                             int m0, int n0, int K, int k0, int t) {
    int row = t >> 1, ch = t & 1;                 // 128 rows x 2 chunks of 16B
    uint32_t off = row * ROWB + ch * 16;
    size_t ak = (size_t)(m0 + row) * K + k0 + ch * 8;
    size_t bk = (size_t)(n0 + row) * K + k0 + ch * 8;
    cp16(base + off,              Ah + ak);
    cp16(base + TILE_B + off,     Al + ak);
    cp16(base + 2 * TILE_B + off, Bh + bk);
    cp16(base + 3 * TILE_B + off, Bl + bk);
    CP_COMMIT();
}

__global__ void __launch_bounds__(256) mma_gemm(const __nv_bfloat16* __restrict__ Ah,
                                                const __nv_bfloat16* __restrict__ Al,
                                                const __nv_bfloat16* __restrict__ Bh,
                                                const __nv_bfloat16* __restrict__ Bl,
                                                const float* __restrict__ bias,
                                                const float* __restrict__ resid,
                                                const float* __restrict__ scale_ptr,
                                                float* __restrict__ outf,
                                                __nv_bfloat16* __restrict__ outh,
                                                __nv_bfloat16* __restrict__ outl,
                                                int M, int N, int K, int mode) {
    __shared__ __align__(16) char smbuf[2 * STG_B];   // 49152 B static
    uint32_t sb = smem_u32(smbuf);
    int t = threadIdx.x, lane = t & 31, wid = t >> 5;
    int m0 = blockIdx.y * 128, n0 = blockIdx.x * 128;
    int wm = (wid >> 1) * 32, wn = (wid & 1) * 64;
    int g = lane >> 2, t4 = lane & 3;

    float c[2][8][4];
    #pragma unroll
    for (int mf = 0; mf < 2; ++mf)
        #pragma unroll
        for (int nf = 0; nf < 8; ++nf)
            #pragma unroll
            for (int j = 0; j < 4; ++j) c[mf][nf][j] = 0.0f;

    const int nit = K >> 4;
    load_stage16(sb, Ah, Al, Bh, Bl, m0, n0, K, 0, t);

    for (int it = 0; it < nit; ++it) {
        if (it + 1 < nit) {
            load_stage16(sb + ((it + 1) & 1) * STG_B, Ah, Al, Bh, Bl, m0, n0, K, (it + 1) << 4, t);
            CP_WAIT(1);
        } else {
            CP_WAIT(0);
        }
        __syncthreads();

        uint32_t bufA_h = sb + (it & 1) * STG_B;
        uint32_t bufA_l = bufA_h + TILE_B;
        uint32_t bufB_h = bufA_h + 2 * TILE_B;
        uint32_t bufB_l = bufA_h + 3 * TILE_B;

        uint32_t cA0 = 4 * t4;        // byte col of k pair (2t4, 2t4+1)
        uint32_t cA1 = 16 + 4 * t4;   // byte col of k pair (8+2t4, 9+2t4)
        uint32_t ah[2][4], al[2][4];
        #pragma unroll
        for (int mf = 0; mf < 2; ++mf) {
            uint32_t r0 = (wm + mf * 16 + g) * ROWB;
            uint32_t r8 = r0 + 8 * ROWB;
            ah[mf][0] = lds32(bufA_h + r0 + cA0);
            ah[mf][1] = lds32(bufA_h + r8 + cA0);
            ah[mf][2] = lds32(bufA_h + r0 + cA1);
            ah[mf][3] = lds32(bufA_h + r8 + cA1);
            al[mf][0] = lds32(bufA_l + r0 + cA0);
            al[mf][1] = lds32(bufA_l + r8 + cA0);
            al[mf][2] = lds32(bufA_l + r0 + cA1);
            al[mf][3] = lds32(bufA_l + r8 + cA1);
        }
        #pragma unroll
        for (int nf = 0; nf < 8; ++nf) {
            uint32_t rn = (wn + nf * 8 + g) * ROWB;
            uint32_t bh0 = lds32(bufB_h + rn + cA0);
            uint32_t bh1 = lds32(bufB_h + rn + cA1);
            uint32_t bl0 = lds32(bufB_l + rn + cA0);
            uint32_t bl1 = lds32(bufB_l + rn + cA1);
            #pragma unroll
            for (int mf = 0; mf < 2; ++mf) {
                mma16816(c[mf][nf], ah[mf], bh0, bh1);
                mma16816(c[mf][nf], al[mf], bh0, bh1);
                mma16816(c[mf][nf], ah[mf], bl0, bl1);
            }
        }
        __syncthreads();
    }

    // ---- epilogue ----
    float scale = scale_ptr ? *scale_ptr : 1.0f;
    #pragma unroll
    for (int mf = 0; mf < 2; ++mf) {
        #pragma unroll
        for (int nf = 0; nf < 8; ++nf) {
            int row = m0 + wm + mf * 16 + g;
            int col = n0 + wn + nf * 8 + 2 * t4;
            float b0 = 0.0f, b1 = 0.0f;
            if (bias) { b0 = bias[col]; b1 = bias[col + 1]; }
            #pragma unroll
            for (int half = 0; half < 2; ++half) {
                int r = row + half * 8;
                float v0 = c[mf][nf][half * 2 + 0] + b0;
                float v1 = c[mf][nf][half * 2 + 1] + b1;
                size_t ro = (size_t)r * N + col;
                if (mode == 1) {
                    float2 rs = *(const float2*)(resid + ro);
                    v0 = rs.x + scale * v0;
                    v1 = rs.y + scale * v1;
                    *(float2*)(outf + ro) = make_float2(v0, v1);
                } else if (mode == 2) {
                    v0 = 0.5f * v0 * (1.0f + erff(v0 * 0.70710678118654752f));
                    v1 = 0.5f * v1 * (1.0f + erff(v1 * 0.70710678118654752f));
                    __nv_bfloat162 h2, l2;
                    h2.x = __float2bfloat16(v0);
                    h2.y = __float2bfloat16(v1);
                    l2.x = __float2bfloat16(v0 - __bfloat162float(h2.x));
                    l2.y = __float2bfloat16(v1 - __bfloat162float(h2.y));
                    *(__nv_bfloat162*)(outh + ro) = h2;
                    *(__nv_bfloat162*)(outl + ro) = l2;
                } else {
                    *(float2*)(outf + ro) = make_float2(v0, v1);
                }
            }
        }
    }
}

// ---------------- attention scores (128x128 tiles, causal tile skip) ----------------
__global__ void __launch_bounds__(256) scores2_k() {
    int bh = blockIdx.z, b = bh / HH, h = bh % HH;
    int s0 = blockIdx.y * 128, t0 = blockIdx.x * 128;
    if (t0 > s0) return;                      // fully masked tile
    __shared__ float Qs[32][132], Ks[32][132];
    const float* qbase = g_qkv + (size_t)b * SS * D3 + h * HS;
    const float* kbase = qbase + DD;
    int t = threadIdx.x, tx = t & 15, ty = t >> 4;
    float acc[8][8] = {};
    for (int kc = 0; kc < 64; kc += 32) {
        #pragma unroll
        for (int p = 0; p < 4; ++p) {
            int q = t + p * 256;
            int row = q >> 3, c4 = (q & 7) * 4;
            float4 qv = *(const float4*)(qbase + (size_t)(s0 + row) * D3 + kc + c4);
            Qs[c4+0][row] = qv.x; Qs[c4+1][row] = qv.y; Qs[c4+2][row] = qv.z; Qs[c4+3][row] = qv.w;
            float4 kv = *(const float4*)(kbase + (size_t)(t0 + row) * D3 + kc + c4);
            Ks[c4+0][row] = kv.x; Ks[c4+1][row] = kv.y; Ks[c4+2][row] = kv.z; Ks[c4+3][row] = kv.w;
        }
        __syncthreads();
        #pragma unroll
        for (int kk = 0; kk < 32; ++kk) {
            float a[8], bb[8];
            *(float4*)&a[0]  = *(const float4*)&Qs[kk][ty * 8];
            *(float4*)&a[4]  = *(const float4*)&Qs[kk][ty * 8 + 4];
            *(float4*)&bb[0] = *(const float4*)&Ks[kk][tx * 8];
            *(float4*)&bb[4] = *(const float4*)&Ks[kk][tx * 8 + 4];
            #pragma unroll
            for (int i = 0; i < 8; i++)
                #pragma unroll
                for (int j = 0; j < 8; j++) acc[i][j] = fmaf(a[i], bb[j], acc[i][j]);
        }
        __syncthreads();
    }
    size_t ob = (size_t)bh * SS * SS;
    #pragma unroll
    for (int i = 0; i < 8; i++) {
        size_t ro = ob + (size_t)(s0 + ty * 8 + i) * SS + t0 + tx * 8;
        *(float4*)(g_att + ro)     = make_float4(acc[i][0]*0.125f, acc[i][1]*0.125f, acc[i][2]*0.125f, acc[i][3]*0.125f);
        *(float4*)(g_att + ro + 4) = make_float4(acc[i][4]*0.125f, acc[i][5]*0.125f, acc[i][6]*0.125f, acc[i][7]*0.125f);
    }
}

// ---------------- causal softmax (in place on g_att) ----------------
__global__ void __launch_bounds__(256) softmax_k() {
    __shared__ float sm[8];
    int row = blockIdx.x;
    int s = row % SS;
    float* p = g_att + (size_t)(row / SS) * SS * SS + (size_t)s * SS;
    int n = s + 1, t = threadIdx.x;
    float mx = -1e30f;
    for (int i = t; i < n; i += 256) mx = fmaxf(mx, p[i]);
    mx = blockMax256(mx, sm);
    float sum = 0.0f;
    for (int i = t; i < n; i += 256) sum += expf(p[i] - mx);
    sum = blockSum256(sum, sm);
    float inv = 1.0f / sum;
    for (int i = t; i < n; i += 256) p[i] = expf(p[i] - mx) * inv;
    for (int i = n + t; i < SS; i += 256) p[i] = 0.0f;
}

// ---------------- AV: o = att @ v -> bf16 split ----------------
__global__ void __launch_bounds__(256) av2_k() {
    int bh = blockIdx.y, b = bh / HH, h = bh % HH;
    int s0 = blockIdx.x * 128;
    __shared__ float Ps[32][132];
    __shared__ float Vs[32][72];
    int t = threadIdx.x, tx = t & 15, ty = t >> 4;
    float acc[8][4] = {};
    const float* vbase = g_qkv + (size_t)b * SS * D3 + 2 * DD + h * HS;
    size_t ab = (size_t)bh * SS * SS;
    int kend = s0 + 128;
    for (int k0 = 0; k0 < kend; k0 += 32) {
        #pragma unroll
        for (int p = 0; p < 4; ++p) {
            int q = t + p * 256;
            int row = q >> 3, c4 = (q & 7) * 4;
            float4 v = *(const float4*)(g_att + ab + (size_t)(s0 + row) * SS + k0 + c4);
            Ps[c4+0][row] = v.x; Ps[c4+1][row] = v.y; Ps[c4+2][row] = v.z; Ps[c4+3][row] = v.w;
        }
        #pragma unroll
        for (int p = 0; p < 2; ++p) {
            int q = t + p * 256;
            int row = q >> 4, c4 = (q & 15) * 4;
            *(float4*)&Vs[row][c4] = *(const float4*)(vbase + (size_t)(k0 + row) * D3 + c4);
        }
        __syncthreads();
        #pragma unroll
        for (int kk = 0; kk < 32; ++kk) {
            float a[8], bb[4];
            *(float4*)&a[0]  = *(const float4*)&Ps[kk][ty * 8];
            *(float4*)&a[4]  = *(const float4*)&Ps[kk][ty * 8 + 4];
            *(float4*)&bb[0] = *(const float4*)&Vs[kk][tx * 4];
            #pragma unroll
            for (int i = 0; i < 8; i++)
                #pragma unroll
                for (int j = 0; j < 4; j++) acc[i][j] = fmaf(a[i], bb[j], acc[i][j]);
        }
        __syncthreads();
    }
    #pragma unroll
    for (int i = 0; i < 8; i++) {
        size_t ro = (size_t)(b * SS + s0 + ty * 8 + i) * DD + h * HS + tx * 4;
        #pragma unroll
        for (int j = 0; j < 4; j += 2) {
            __nv_bfloat162 h2, l2;
            h2.x = __float2bfloat16(acc[i][j]);
            h2.y = __float2bfloat16(acc[i][j+1]);
            l2.x = __float2bfloat16(acc[i][j]   - __bfloat162float(h2.x));
            l2.y = __float2bfloat16(acc[i][j+1] - __bfloat162float(h2.y));
            *(__nv_bfloat162*)(g_oh + ro + j) = h2;
            *(__nv_bfloat162*)(g_ol + ro + j) = l2;
        }
    }
}

// ---------------- loss ----------------
__global__ void __launch_bounds__(256) rowloss_k(const float* __restrict__ logits,
                                                 const int* __restrict__ targets) {
    __shared__ float sm[8];
    int m = blockIdx.x, t = threadIdx.x;
    const float* p = logits + (size_t)m * VV;
    float mx = -1e30f;
    for (int i = t; i < VV; i += 256) mx = fmaxf(mx, p[i]);
    mx = blockMax256(mx, sm);
    float sum = 0.0f;
    for (int i = t; i < VV; i += 256) sum += expf(p[i] - mx);
    sum = blockSum256(sum, sm);
    if (t == 0) {
        float lt = p[targets[m]];
        g_rowloss[m] = -(lt - mx - logf(sum));
    }
}

__global__ void __launch_bounds__(256) lossreduce_k(float* __restrict__ out) {
    __shared__ float sm[8];
    float s = 0.0f;
    for (int i = threadIdx.x; i < MR; i += 256) s += g_rowloss[i];
    s = blockSum256(s, sm);
    if (threadIdx.x == 0) out[0] = s / (float)MR;
}

// ---------------- launch ----------------
extern "C" void kernel_launch(void* const* d_in, const int* in_sizes, int n_in,
                              void* d_out, int out_size) {
    const int*   idx     = (const int*)  d_in[0];
    const int*   targets = (const int*)  d_in[1];
    const float* tok     = (const float*)d_in[2];
    const float* pos     = (const float*)d_in[3];
    const float* Wq      = (const float*)d_in[4];
    const float* bq      = (const float*)d_in[5];
    const float* Wk      = (const float*)d_in[6];
    const float* bk      = (const float*)d_in[7];
    const float* Wv      = (const float*)d_in[8];
    const float* bv      = (const float*)d_in[9];
    const float* Wo      = (const float*)d_in[10];
    const float* bo      = (const float*)d_in[11];
    const float* ln1g    = (const float*)d_in[12];
    const float* ln1b    = (const float*)d_in[13];
    const float* ln2g    = (const float*)d_in[14];
    const float* ln2b    = (const float*)d_in[15];
    const float* W1      = (const float*)d_in[16];
    const float* b1      = (const float*)d_in[17];
    const float* W2      = (const float*)d_in[18];
    const float* b2      = (const float*)d_in[19];
    const float* W3      = (const float*)d_in[20];
    const float* b3      = (const float*)d_in[21];
    const float* att_sc  = (const float*)d_in[22];
    const float* ffd_sc  = (const float*)d_in[23];
    const float* lnfg    = (const float*)d_in[24];
    const float* lnfb    = (const float*)d_in[25];
    float* out = (float*)d_out;

    float *px, *pqkv, *pbq;
    __nv_bfloat16 *pah, *pal, *poh, *pol, *pf1h, *pf1l, *pf2h, *pf2l;
    __nv_bfloat16 *pwqkvh, *pwqkvl, *pwoh, *pwol, *pw1h, *pw1l, *pw2h, *pw2l, *pw3h, *pw3l, *pwvh, *pwvl;
    cudaGetSymbolAddress((void**)&px,     g_x);
    cudaGetSymbolAddress((void**)&pqkv,   g_qkv);
    cudaGetSymbolAddress((void**)&pbq,    g_bqkv);
    cudaGetSymbolAddress((void**)&pah,    g_ah);
    cudaGetSymbolAddress((void**)&pal,    g_al);
    cudaGetSymbolAddress((void**)&poh,    g_oh);
    cudaGetSymbolAddress((void**)&pol,    g_ol);
    cudaGetSymbolAddress((void**)&pf1h,   g_f1h);
    cudaGetSymbolAddress((void**)&pf1l,   g_f1l);
    cudaGetSymbolAddress((void**)&pf2h,   g_f2h);
    cudaGetSymbolAddress((void**)&pf2l,   g_f2l);
    cudaGetSymbolAddress((void**)&pwqkvh, g_wqkvh);
    cudaGetSymbolAddress((void**)&pwqkvl, g_wqkvl);
    cudaGetSymbolAddress((void**)&pwoh,   g_woh);
    cudaGetSymbolAddress((void**)&pwol,   g_wol);
    cudaGetSymbolAddress((void**)&pw1h,   g_w1h);
    cudaGetSymbolAddress((void**)&pw1l,   g_w1l);
    cudaGetSymbolAddress((void**)&pw2h,   g_w2h);
    cudaGetSymbolAddress((void**)&pw2l,   g_w2l);
    cudaGetSymbolAddress((void**)&pw3h,   g_w3h);
    cudaGetSymbolAddress((void**)&pw3l,   g_w3l);
    cudaGetSymbolAddress((void**)&pwvh,   g_wvh);
    cudaGetSymbolAddress((void**)&pwvl,   g_wvl);

    dim3 tb(32, 8);
    // ---- weight prep ----
    tsplit_qkv_k<<<dim3(24, 2, LL * HH), tb>>>(Wq, pwqkvh, pwqkvl, 0);
    tsplit_qkv_k<<<dim3(24, 2, LL * HH), tb>>>(Wk, pwqkvh, pwqkvl, DD);
    tsplit_qkv_k<<<dim3(24, 2, LL * HH), tb>>>(Wv, pwqkvh, pwqkvl, 2 * DD);
    tsplit_k<<<dim3(DD / 32,  DD / 32,  LL), tb>>>(Wo, pwoh, pwol, DD, DD);
    tsplit_k<<<dim3(DD / 32,  F1N / 32, LL), tb>>>(W1, pw1h, pw1l, DD, F1N);
    tsplit_k<<<dim3(F1N / 32, F2N / 32, LL), tb>>>(W2, pw2h, pw2l, F1N, F2N);
    tsplit_k<<<dim3(F2N / 32, DD / 32,  LL), tb>>>(W3, pw3h, pw3l, F2N, DD);
    split_k<<<(VV * DD + 255) / 256, 256>>>(tok, pwvh, pwvl, VV * DD);
    prep_b_k<<<(LL * D3 + 255) / 256, 256>>>(bq, bk, bv);
    embed_k<<<(MR * DD + 255) / 256, 256>>>(idx, tok, pos);

    for (int l = 0; l < LL; l++) {
        ln_k<<<MR, 256>>>(px, ln1g + l * DD, ln1b + l * DD, pah, pal);
        // QKV: [4096,768] x [2304,768]^T
        mma_gemm<<<dim3(D3 / 128, MR / 128), 256>>>(
            pah, pal, pwqkvh + (size_t)l * D3 * DD, pwqkvl + (size_t)l * D3 * DD,
            pbq + l * D3, nullptr, nullptr, pqkv, nullptr, nullptr, MR, D3, DD, 0);
        scores2_k<<<dim3(SS / 128, SS / 128, BB * HH), 256>>>();
        softmax_k<<<BB * HH * SS, 256>>>();
        av2_k<<<dim3(SS / 128, BB * HH), 256>>>();
        // x += att_scale * (o @ Wo + bo)
        mma_gemm<<<dim3(DD / 128, MR / 128), 256>>>(
            poh, pol, pwoh + (size_t)l * DD * DD, pwol + (size_t)l * DD * DD,
            bo + l * DD, px, att_sc + l, px, nullptr, nullptr, MR, DD, DD, 1);
        ln_k<<<MR, 256>>>(px, ln2g + l * DD, ln2b + l * DD, pah, pal);
        mma_gemm<<<dim3(F1N / 128, MR / 128), 256>>>(
            pah, pal, pw1h + (size_t)l * F1N * DD, pw1l + (size_t)l * F1N * DD,
            b1 + l * F1N, nullptr, nullptr, nullptr, pf1h, pf1l, MR, F1N, DD, 2);
        mma_gemm<<<dim3(F2N / 128, MR / 128), 256>>>(
            pf1h, pf1l, pw2h + (size_t)l * F2N * F1N, pw2l + (size_t)l * F2N * F1N,
            b2 + l * F2N, nullptr, nullptr, nullptr, pf2h, pf2l, MR, F2N, F1N, 2);
        mma_gemm<<<dim3(DD / 128, MR / 128), 256>>>(
            pf2h, pf2l, pw3h + (size_t)l * DD * F2N, pw3l + (size_t)l * DD * F2N,
            b3 + l * DD, px, ffd_sc + l, px, nullptr, nullptr, MR, DD, F2N, 1);
    }

    ln_k<<<MR, 256>>>(px, lnfg, lnfb, pah, pal);
    mma_gemm<<<dim3(VV / 128, MR / 128), 256>>>(
        pah, pal, pwvh, pwvl, nullptr, nullptr, nullptr, out, nullptr, nullptr, MR, VV, DD, 0);
    rowloss_k<<<MR, 256>>>(out, targets);
    if ((long long)out_size > (long long)MR * VV)
        lossreduce_k<<<1, 256>>>(out + (size_t)MR * VV);
}

// round 7
// speedup vs baseline: 2.0403x; 1.0007x over previous
#include <cuda_runtime.h>
#include <cuda_bf16.h>
#include <stdint.h>
#include <stddef.h>
#include <math.h>

// ---------------- problem constants ----------------
#define BB   4
#define SS   1024
#define DD   768
#define LL   12
#define HH   12
#define HS   64
#define VV   32000
#define MR   (BB*SS)        // 4096 rows
#define D3   (3*DD)         // 2304 (qkv concat)
#define F1N  (4*DD)         // 3072
#define F2N  (3*DD)         // 2304

// ---------------- scratch (static device allocs) ----------------
__device__ float g_x   [MR*DD];                 // residual stream fp32
__device__ __nv_bfloat16 g_ah[MR*DD];           // ln output split hi
__device__ __nv_bfloat16 g_al[MR*DD];           // ln output split lo
__device__ float g_qkv [MR*D3];
__device__ float g_att [(size_t)BB*HH*SS*SS];   // 201 MB
__device__ __nv_bfloat16 g_oh[MR*DD];
__device__ __nv_bfloat16 g_ol[MR*DD];
__device__ __nv_bfloat16 g_f1h[(size_t)MR*F1N];
__device__ __nv_bfloat16 g_f1l[(size_t)MR*F1N];
__device__ __nv_bfloat16 g_f2h[(size_t)MR*F2N];
__device__ __nv_bfloat16 g_f2l[(size_t)MR*F2N];
// weights, transposed to [N,K], split bf16 hi/lo
__device__ __nv_bfloat16 g_wqkvh[(size_t)LL*D3*DD];
__device__ __nv_bfloat16 g_wqkvl[(size_t)LL*D3*DD];
__device__ __nv_bfloat16 g_woh[(size_t)LL*DD*DD];
__device__ __nv_bfloat16 g_wol[(size_t)LL*DD*DD];
__device__ __nv_bfloat16 g_w1h[(size_t)LL*F1N*DD];
__device__ __nv_bfloat16 g_w1l[(size_t)LL*F1N*DD];
__device__ __nv_bfloat16 g_w2h[(size_t)LL*F2N*F1N];
__device__ __nv_bfloat16 g_w2l[(size_t)LL*F2N*F1N];
__device__ __nv_bfloat16 g_w3h[(size_t)LL*DD*F2N];
__device__ __nv_bfloat16 g_w3l[(size_t)LL*DD*F2N];
__device__ __nv_bfloat16 g_wvh[(size_t)VV*DD];   // tok_emb (already [N,K])
__device__ __nv_bfloat16 g_wvl[(size_t)VV*DD];
__device__ float g_bqkv[LL*D3];
__device__ float g_rowloss[MR];

// ================= PTX helpers (sm_100 base target safe) =================
__device__ __forceinline__ uint32_t smem_u32(const void* p) {
    uint32_t a;
    asm("{ .reg .u64 t; cvta.to.shared.u64 t, %1; cvt.u32.u64 %0, t; }" : "=r"(a) : "l"(p));
    return a;
}
__device__ __forceinline__ void cp16(uint32_t d, const void* s) {
    asm volatile("cp.async.cg.shared.global [%0], [%1], 16;" :: "r"(d), "l"(s));
}
#define CP_COMMIT() asm volatile("cp.async.commit_group;" ::: "memory")
#define CP_WAIT(n)  asm volatile("cp.async.wait_group %0;" :: "n"(n) : "memory")

// ldmatrix: four 8x8 b16 matrices; lane i supplies row address
__device__ __forceinline__ void ldsm4(uint32_t* r, uint32_t addr) {
    asm volatile("ldmatrix.sync.aligned.m8n8.x4.shared.b16 {%0,%1,%2,%3}, [%4];"
                 : "=r"(r[0]), "=r"(r[1]), "=r"(r[2]), "=r"(r[3]) : "r"(addr));
}

// D = A(16x16 row) * B(16x8 col) + D, bf16 in, fp32 out
__device__ __forceinline__ void mma16816(float* c, const uint32_t* a, uint32_t b0, uint32_t b1) {
    asm volatile(
        "mma.sync.aligned.m16n8k16.row.col.f32.bf16.bf16.f32 "
        "{%0,%1,%2,%3}, {%4,%5,%6,%7}, {%8,%9}, {%0,%1,%2,%3};"
        : "+f"(c[0]), "+f"(c[1]), "+f"(c[2]), "+f"(c[3])
        : "r"(a[0]), "r"(a[1]), "r"(a[2]), "r"(a[3]), "r"(b0), "r"(b1));
}

// ---------------- block reductions (deterministic) ----------------
__device__ __forceinline__ float blockSum256(float v, float* sm) {
    #pragma unroll
    for (int o = 16; o > 0; o >>= 1) v += __shfl_down_sync(0xffffffffu, v, o);
    int lane = threadIdx.x & 31, w = threadIdx.x >> 5;
    if (lane == 0) sm[w] = v;
    __syncthreads();
    if (threadIdx.x < 32) {
        v = (lane < 8) ? sm[lane] : 0.0f;
        #pragma unroll
        for (int o = 4; o > 0; o >>= 1) v += __shfl_down_sync(0xffffffffu, v, o);
        if (lane == 0) sm[0] = v;
    }
    __syncthreads();
    float r = sm[0];
    __syncthreads();
    return r;
}
__device__ __forceinline__ float blockMax256(float v, float* sm) {
    #pragma unroll
    for (int o = 16; o > 0; o >>= 1) v = fmaxf(v, __shfl_down_sync(0xffffffffu, v, o));
    int lane = threadIdx.x & 31, w = threadIdx.x >> 5;
    if (lane == 0) sm[w] = v;
    __syncthreads();
    if (threadIdx.x < 32) {
        v = (lane < 8) ? sm[lane] : -1e30f;
        #pragma unroll
        for (int o = 4; o > 0; o >>= 1) v = fmaxf(v, __shfl_down_sync(0xffffffffu, v, o));
        if (lane == 0) sm[0] = v;
    }
    __syncthreads();
    float r = sm[0];
    __syncthreads();
    return r;
}

// ---------------- weight prep: tiled transpose + bf16 split ----------------
__global__ void __launch_bounds__(256) tsplit_k(const float* __restrict__ src,
                                                __nv_bfloat16* __restrict__ dh,
                                                __nv_bfloat16* __restrict__ dl,
                                                int K, int N) {
    __shared__ float tile[32][33];
    int k0 = blockIdx.x * 32, n0 = blockIdx.y * 32;
    size_t so = (size_t)blockIdx.z * K * N;
    int tx = threadIdx.x, ty = threadIdx.y;   // (32,8)
    #pragma unroll
    for (int r = 0; r < 32; r += 8)
        tile[ty + r][tx] = src[so + (size_t)(k0 + ty + r) * N + n0 + tx];
    __syncthreads();
    #pragma unroll
    for (int r = 0; r < 32; r += 8) {
        float v = tile[tx][ty + r];
        size_t di = so + (size_t)(n0 + ty + r) * K + k0 + tx;
        __nv_bfloat16 h = __float2bfloat16(v);
        dh[di] = h;
        dl[di] = __float2bfloat16(v - __bfloat162float(h));
    }
}

// qkv: src [L*HH][DD][HS]; dst row n = nbase + h*HS + e, col k = d
__global__ void __launch_bounds__(256) tsplit_qkv_k(const float* __restrict__ src,
                                                    __nv_bfloat16* __restrict__ dh,
                                                    __nv_bfloat16* __restrict__ dl,
                                                    int nbase) {
    __shared__ float tile[32][33];
    int l = blockIdx.z / HH, h = blockIdx.z % HH;
    int k0 = blockIdx.x * 32, n0 = blockIdx.y * 32;
    const float* s = src + (size_t)blockIdx.z * DD * HS;
    size_t dbase = (size_t)l * D3 * DD + (size_t)(nbase + h * HS) * DD;
    int tx = threadIdx.x, ty = threadIdx.y;
    #pragma unroll
    for (int r = 0; r < 32; r += 8)
        tile[ty + r][tx] = s[(size_t)(k0 + ty + r) * HS + n0 + tx];
    __syncthreads();
    #pragma unroll
    for (int r = 0; r < 32; r += 8) {
        float v = tile[tx][ty + r];
        size_t di = dbase + (size_t)(n0 + ty + r) * DD + k0 + tx;
        __nv_bfloat16 hi = __float2bfloat16(v);
        dh[di] = hi;
        dl[di] = __float2bfloat16(v - __bfloat162float(hi));
    }
}

__global__ void __launch_bounds__(256) split_k(const float* __restrict__ src,
                                               __nv_bfloat16* __restrict__ dh,
                                               __nv_bfloat16* __restrict__ dl, int n) {
    int i = blockIdx.x * 256 + threadIdx.x;
    if (i >= n) return;
    float v = src[i];
    __nv_bfloat16 h = __float2bfloat16(v);
    dh[i] = h;
    dl[i] = __float2bfloat16(v - __bfloat162float(h));
}

__global__ void __launch_bounds__(256) prep_b_k(const float* __restrict__ bq,
                                                const float* __restrict__ bk,
                                                const float* __restrict__ bv) {
    int i = blockIdx.x * 256 + threadIdx.x;
    if (i >= LL * D3) return;
    int l = i / D3, n = i % D3;
    int which = n / DD;
    int h = (n % DD) / HS;
    int e = n % HS;
    const float* b = (which == 0) ? bq : ((which == 1) ? bk : bv);
    g_bqkv[i] = b[(l * HH + h) * HS + e];
}

// ---------------- embedding ----------------
__global__ void __launch_bounds__(256) embed_k(const int* __restrict__ idx,
                                               const float* __restrict__ tok,
                                               const float* __restrict__ pos) {
    int i = blockIdx.x * 256 + threadIdx.x;
    if (i >= MR * DD) return;
    int m = i / DD, d = i % DD;
    int s = m % SS;
    g_x[i] = tok[(size_t)idx[m] * DD + d] + pos[s * DD + d] * 0.03608439182435161f;
}

// ---------------- layernorm -> split bf16 ----------------
__global__ void __launch_bounds__(256) ln_k(const float* __restrict__ x,
                                            const float* __restrict__ g,
                                            const float* __restrict__ b,
                                            __nv_bfloat16* __restrict__ oh,
                                            __nv_bfloat16* __restrict__ ol) {
    __shared__ float sm[8];
    int r = blockIdx.x, t = threadIdx.x;
    const float* xr = x + (size_t)r * DD;
    float v0 = xr[t], v1 = xr[t + 256], v2 = xr[t + 512];
    float mu = blockSum256(v0 + v1 + v2, sm) * (1.0f / (float)DD);
    float d0 = v0 - mu, d1 = v1 - mu, d2 = v2 - mu;
    float var = blockSum256(d0 * d0 + d1 * d1 + d2 * d2, sm) * (1.0f / (float)DD);
    float rs = rsqrtf(var + 1e-5f);
    size_t ro = (size_t)r * DD;
    #pragma unroll
    for (int p = 0; p < 3; p++) {
        int c = t + p * 256;
        float dv = (p == 0 ? d0 : (p == 1 ? d1 : d2));
        float v = dv * rs * g[c] + b[c];
        __nv_bfloat16 h = __float2bfloat16(v);
        oh[ro + c] = h;
        ol[ro + c] = __float2bfloat16(v - __bfloat162float(h));
    }
}

// ---------------- mma.sync split-bf16 GEMM (ldmatrix fragments) ----------------
// C[M,N] = epi(Ah@Bh^T + Ah@Bl^T + Al@Bh^T + bias)
// A: [M,K] bf16 row-major; B: [N,K] bf16 row-major.
// CTA tile 128x128, K=16 per stage, double-buffered cp.async, static 48KB smem.
// 8 warps, each 32(M) x 64(N). ROWB=48 pad: ldmatrix phases conflict-free.
#define ROWB   48
#define TILE_B (128*ROWB)     // 6144
#define STG_B  (4*TILE_B)     // 24576

__device__ __forceinline__ void load_stage16(uint32_t base,
                                             const __nv_bfloat16* __restrict__ Ah,
                                             const __nv_bfloat16* __restrict__ Al,
                                             const __nv_bfloat16* __restrict__ Bh,
                                             const __nv_bfloat16* __restrict__ Bl,
                                             int m0, int n0, int K, int k0, int t) {
    int row = t >> 1, ch = t & 1;                 // 128 rows x 2 chunks of 16B
    uint32_t off = row * ROWB + ch * 16;
    size_t ak = (size_t)(m0 + row) * K + k0 + ch * 8;
    size_t bk = (size_t)(n0 + row) * K + k0 + ch * 8;
    cp16(base + off,              Ah + ak);
    cp16(base + TILE_B + off,     Al + ak);
    cp16(base + 2 * TILE_B + off, Bh + bk);
    cp16(base + 3 * TILE_B + off, Bl + bk);
    CP_COMMIT();
}

__global__ void __launch_bounds__(256) mma_gemm(const __nv_bfloat16* __restrict__ Ah,
                                                const __nv_bfloat16* __restrict__ Al,
                                                const __nv_bfloat16* __restrict__ Bh,
                                                const __nv_bfloat16* __restrict__ Bl,
                                                const float* __restrict__ bias,
                                                const float* __restrict__ resid,
                                                const float* __restrict__ scale_ptr,
                                                float* __restrict__ outf,
                                                __nv_bfloat16* __restrict__ outh,
                                                __nv_bfloat16* __restrict__ outl,
                                                int M, int N, int K, int mode) {
    __shared__ __align__(16) char smbuf[2 * STG_B];   // 49152 B static
    uint32_t sb = smem_u32(smbuf);
    int t = threadIdx.x, lane = t & 31, wid = t >> 5;
    int m0 = blockIdx.y * 128, n0 = blockIdx.x * 128;
    int wm = (wid >> 1) * 32, wn = (wid & 1) * 64;
    int g = lane >> 2, t4 = lane & 3;

    // ldmatrix addressing: lane -> (row in 16-row group, 16B column)
    uint32_t lrow = lane & 15;
    uint32_t lcol = (lane >> 4) << 4;   // 0 or 16
    uint32_t aoff = (wm + lrow) * ROWB + lcol;
    uint32_t boff = (wn + lrow) * ROWB + lcol;

    float c[2][8][4];
    #pragma unroll
    for (int mf = 0; mf < 2; ++mf)
        #pragma unroll
        for (int nf = 0; nf < 8; ++nf)
            #pragma unroll
            for (int j = 0; j < 4; ++j) c[mf][nf][j] = 0.0f;

    const int nit = K >> 4;
    load_stage16(sb, Ah, Al, Bh, Bl, m0, n0, K, 0, t);

    for (int it = 0; it < nit; ++it) {
        if (it + 1 < nit) {
            load_stage16(sb + ((it + 1) & 1) * STG_B, Ah, Al, Bh, Bl, m0, n0, K, (it + 1) << 4, t);
            CP_WAIT(1);
        } else {
            CP_WAIT(0);
        }
        __syncthreads();

        uint32_t bufA_h = sb + (it & 1) * STG_B;
        uint32_t bufA_l = bufA_h + TILE_B;
        uint32_t bufB_h = bufA_h + 2 * TILE_B;
        uint32_t bufB_l = bufA_h + 3 * TILE_B;

        uint32_t ah[2][4], al[2][4], bh[4][4], bl[4][4];
        #pragma unroll
        for (int mf = 0; mf < 2; ++mf) {
            ldsm4(ah[mf], bufA_h + aoff + mf * 16 * ROWB);
            ldsm4(al[mf], bufA_l + aoff + mf * 16 * ROWB);
        }
        #pragma unroll
        for (int nb = 0; nb < 4; ++nb) {
            ldsm4(bh[nb], bufB_h + boff + nb * 16 * ROWB);
            ldsm4(bl[nb], bufB_l + boff + nb * 16 * ROWB);
        }

        #pragma unroll
        for (int nb = 0; nb < 4; ++nb) {
            #pragma unroll
            for (int h2 = 0; h2 < 2; ++h2) {
                int nf = nb * 2 + h2;
                uint32_t bh0 = bh[nb][h2], bh1 = bh[nb][h2 + 2];
                uint32_t bl0 = bl[nb][h2], bl1 = bl[nb][h2 + 2];
                #pragma unroll
                for (int mf = 0; mf < 2; ++mf) {
                    mma16816(c[mf][nf], ah[mf], bh0, bh1);
                    mma16816(c[mf][nf], al[mf], bh0, bh1);
                    mma16816(c[mf][nf], ah[mf], bl0, bl1);
                }
            }
        }
        __syncthreads();
    }

    // ---- epilogue ----
    float scale = scale_ptr ? *scale_ptr : 1.0f;
    #pragma unroll
    for (int mf = 0; mf < 2; ++mf) {
        #pragma unroll
        for (int nf = 0; nf < 8; ++nf) {
            int row = m0 + wm + mf * 16 + g;
            int col = n0 + wn + nf * 8 + 2 * t4;
            float b0 = 0.0f, b1 = 0.0f;
            if (bias) { b0 = bias[col]; b1 = bias[col + 1]; }
            #pragma unroll
            for (int half = 0; half < 2; ++half) {
                int r = row + half * 8;
                float v0 = c[mf][nf][half * 2 + 0] + b0;
                float v1 = c[mf][nf][half * 2 + 1] + b1;
                size_t ro = (size_t)r * N + col;
                if (mode == 1) {
                    float2 rs = *(const float2*)(resid + ro);
                    v0 = rs.x + scale * v0;
                    v1 = rs.y + scale * v1;
                    *(float2*)(outf + ro) = make_float2(v0, v1);
                } else if (mode == 2) {
                    v0 = 0.5f * v0 * (1.0f + erff(v0 * 0.70710678118654752f));
                    v1 = 0.5f * v1 * (1.0f + erff(v1 * 0.70710678118654752f));
                    __nv_bfloat162 h2, l2;
                    h2.x = __float2bfloat16(v0);
                    h2.y = __float2bfloat16(v1);
                    l2.x = __float2bfloat16(v0 - __bfloat162float(h2.x));
                    l2.y = __float2bfloat16(v1 - __bfloat162float(h2.y));
                    *(__nv_bfloat162*)(outh + ro) = h2;
                    *(__nv_bfloat162*)(outl + ro) = l2;
                } else {
                    *(float2*)(outf + ro) = make_float2(v0, v1);
                }
            }
        }
    }
}

// ---------------- attention scores (128x128 tiles, causal tile skip) ----------------
__global__ void __launch_bounds__(256) scores2_k() {
    int bh = blockIdx.z, b = bh / HH, h = bh % HH;
    int s0 = blockIdx.y * 128, t0 = blockIdx.x * 128;
    if (t0 > s0) return;                      // fully masked tile
    __shared__ float Qs[32][132], Ks[32][132];
    const float* qbase = g_qkv + (size_t)b * SS * D3 + h * HS;
    const float* kbase = qbase + DD;
    int t = threadIdx.x, tx = t & 15, ty = t >> 4;
    float acc[8][8] = {};
    for (int kc = 0; kc < 64; kc += 32) {
        #pragma unroll
        for (int p = 0; p < 4; ++p) {
            int q = t + p * 256;
            int row = q >> 3, c4 = (q & 7) * 4;
            float4 qv = *(const float4*)(qbase + (size_t)(s0 + row) * D3 + kc + c4);
            Qs[c4+0][row] = qv.x; Qs[c4+1][row] = qv.y; Qs[c4+2][row] = qv.z; Qs[c4+3][row] = qv.w;
            float4 kv = *(const float4*)(kbase + (size_t)(t0 + row) * D3 + kc + c4);
            Ks[c4+0][row] = kv.x; Ks[c4+1][row] = kv.y; Ks[c4+2][row] = kv.z; Ks[c4+3][row] = kv.w;
        }
        __syncthreads();
        #pragma unroll
        for (int kk = 0; kk < 32; ++kk) {
            float a[8], bb[8];
            *(float4*)&a[0]  = *(const float4*)&Qs[kk][ty * 8];
            *(float4*)&a[4]  = *(const float4*)&Qs[kk][ty * 8 + 4];
            *(float4*)&bb[0] = *(const float4*)&Ks[kk][tx * 8];
            *(float4*)&bb[4] = *(const float4*)&Ks[kk][tx * 8 + 4];
            #pragma unroll
            for (int i = 0; i < 8; i++)
                #pragma unroll
                for (int j = 0; j < 8; j++) acc[i][j] = fmaf(a[i], bb[j], acc[i][j]);
        }
        __syncthreads();
    }
    size_t ob = (size_t)bh * SS * SS;
    #pragma unroll
    for (int i = 0; i < 8; i++) {
        size_t ro = ob + (size_t)(s0 + ty * 8 + i) * SS + t0 + tx * 8;
        *(float4*)(g_att + ro)     = make_float4(acc[i][0]*0.125f, acc[i][1]*0.125f, acc[i][2]*0.125f, acc[i][3]*0.125f);
        *(float4*)(g_att + ro + 4) = make_float4(acc[i][4]*0.125f, acc[i][5]*0.125f, acc[i][6]*0.125f, acc[i][7]*0.125f);
    }
}

// ---------------- causal softmax (register-resident, in place) ----------------
__global__ void __launch_bounds__(256) softmax_k() {
    __shared__ float sm[8];
    int row = blockIdx.x;
    int s = row % SS;
    float* p = g_att + (size_t)(row / SS) * SS * SS + (size_t)s * SS;
    int n = s + 1, t = threadIdx.x;
    int ntile = ((s >> 7) + 1) << 7;          // av reads cols [0, ntile)
    float v[4];
    #pragma unroll
    for (int q = 0; q < 4; ++q) {
        int i = t + q * 256;
        v[q] = (i < n) ? p[i] : -1e30f;
    }
    float mx = fmaxf(fmaxf(v[0], v[1]), fmaxf(v[2], v[3]));
    mx = blockMax256(mx, sm);
    float e[4];
    float sum = 0.0f;
    #pragma unroll
    for (int q = 0; q < 4; ++q) {
        int i = t + q * 256;
        e[q] = (i < n) ? expf(v[q] - mx) : 0.0f;
        sum += e[q];
    }
    sum = blockSum256(sum, sm);
    float inv = 1.0f / sum;
    #pragma unroll
    for (int q = 0; q < 4; ++q) {
        int i = t + q * 256;
        if (i < n)          p[i] = e[q] * inv;
        else if (i < ntile) p[i] = 0.0f;
    }
}

// ---------------- AV: o = att @ v -> bf16 split ----------------
__global__ void __launch_bounds__(256) av2_k() {
    int bh = blockIdx.y, b = bh / HH, h = bh % HH;
    int s0 = blockIdx.x * 128;
    __shared__ float Ps[32][132];
    __shared__ float Vs[32][72];
    int t = threadIdx.x, tx = t & 15, ty = t >> 4;
    float acc[8][4] = {};
    const float* vbase = g_qkv + (size_t)b * SS * D3 + 2 * DD + h * HS;
    size_t ab = (size_t)bh * SS * SS;
    int kend = s0 + 128;
    for (int k0 = 0; k0 < kend; k0 += 32) {
        #pragma unroll
        for (int p = 0; p < 4; ++p) {
            int q = t + p * 256;
            int row = q >> 3, c4 = (q & 7) * 4;
            float4 v = *(const float4*)(g_att + ab + (size_t)(s0 + row) * SS + k0 + c4);
            Ps[c4+0][row] = v.x; Ps[c4+1][row] = v.y; Ps[c4+2][row] = v.z; Ps[c4+3][row] = v.w;
        }
        #pragma unroll
        for (int p = 0; p < 2; ++p) {
            int q = t + p * 256;
            int row = q >> 4, c4 = (q & 15) * 4;
            *(float4*)&Vs[row][c4] = *(const float4*)(vbase + (size_t)(k0 + row) * D3 + c4);
        }
        __syncthreads();
        #pragma unroll
        for (int kk = 0; kk < 32; ++kk) {
            float a[8], bb[4];
            *(float4*)&a[0]  = *(const float4*)&Ps[kk][ty * 8];
            *(float4*)&a[4]  = *(const float4*)&Ps[kk][ty * 8 + 4];
            *(float4*)&bb[0] = *(const float4*)&Vs[kk][tx * 4];
            #pragma unroll
            for (int i = 0; i < 8; i++)
                #pragma unroll
                for (int j = 0; j < 4; j++) acc[i][j] = fmaf(a[i], bb[j], acc[i][j]);
        }
        __syncthreads();
    }
    #pragma unroll
    for (int i = 0; i < 8; i++) {
        size_t ro = (size_t)(b * SS + s0 + ty * 8 + i) * DD + h * HS + tx * 4;
        #pragma unroll
        for (int j = 0; j < 4; j += 2) {
            __nv_bfloat162 h2, l2;
            h2.x = __float2bfloat16(acc[i][j]);
            h2.y = __float2bfloat16(acc[i][j+1]);
            l2.x = __float2bfloat16(acc[i][j]   - __bfloat162float(h2.x));
            l2.y = __float2bfloat16(acc[i][j+1] - __bfloat162float(h2.y));
            *(__nv_bfloat162*)(g_oh + ro + j) = h2;
            *(__nv_bfloat162*)(g_ol + ro + j) = l2;
        }
    }
}

// ---------------- loss: single-pass online logsumexp ----------------
__global__ void __launch_bounds__(256) rowloss_k(const float* __restrict__ logits,
                                                 const int* __restrict__ targets) {
    __shared__ float smM[8], smS[8];
    int m = blockIdx.x, t = threadIdx.x;
    const float* p = logits + (size_t)m * VV;
    float mx = -1e30f, s = 0.0f;
    for (int i = t; i < VV; i += 256) {
        float x = p[i];
        if (x <= mx) {
            s += expf(x - mx);
        } else {
            s = s * expf(mx - x) + 1.0f;
            mx = x;
        }
    }
    // warp combine (m,s)
    #pragma unroll
    for (int o = 16; o > 0; o >>= 1) {
        float m2 = __shfl_down_sync(0xffffffffu, mx, o);
        float s2 = __shfl_down_sync(0xffffffffu, s, o);
        float mn = fmaxf(mx, m2);
        s = s * expf(mx - mn) + s2 * expf(m2 - mn);
        mx = mn;
    }
    int lane = t & 31, w = t >> 5;
    if (lane == 0) { smM[w] = mx; smS[w] = s; }
    __syncthreads();
    if (t == 0) {
        float M = smM[0], S = smS[0];
        #pragma unroll
        for (int w2 = 1; w2 < 8; ++w2) {
            float m2 = smM[w2], s2 = smS[w2];
            float mn = fmaxf(M, m2);
            S = S * expf(M - mn) + s2 * expf(m2 - mn);
            M = mn;
        }
        float lt = p[targets[m]];
        g_rowloss[m] = -(lt - M - logf(S));
    }
}

__global__ void __launch_bounds__(256) lossreduce_k(float* __restrict__ out) {
    __shared__ float sm[8];
    float s = 0.0f;
    for (int i = threadIdx.x; i < MR; i += 256) s += g_rowloss[i];
    s = blockSum256(s, sm);
    if (threadIdx.x == 0) out[0] = s / (float)MR;
}

// ---------------- launch ----------------
extern "C" void kernel_launch(void* const* d_in, const int* in_sizes, int n_in,
                              void* d_out, int out_size) {
    const int*   idx     = (const int*)  d_in[0];
    const int*   targets = (const int*)  d_in[1];
    const float* tok     = (const float*)d_in[2];
    const float* pos     = (const float*)d_in[3];
    const float* Wq      = (const float*)d_in[4];
    const float* bq      = (const float*)d_in[5];
    const float* Wk      = (const float*)d_in[6];
    const float* bk      = (const float*)d_in[7];
    const float* Wv      = (const float*)d_in[8];
    const float* bv      = (const float*)d_in[9];
    const float* Wo      = (const float*)d_in[10];
    const float* bo      = (const float*)d_in[11];
    const float* ln1g    = (const float*)d_in[12];
    const float* ln1b    = (const float*)d_in[13];
    const float* ln2g    = (const float*)d_in[14];
    const float* ln2b    = (const float*)d_in[15];
    const float* W1      = (const float*)d_in[16];
    const float* b1      = (const float*)d_in[17];
    const float* W2      = (const float*)d_in[18];
    const float* b2      = (const float*)d_in[19];
    const float* W3      = (const float*)d_in[20];
    const float* b3      = (const float*)d_in[21];
    const float* att_sc  = (const float*)d_in[22];
    const float* ffd_sc  = (const float*)d_in[23];
    const float* lnfg    = (const float*)d_in[24];
    const float* lnfb    = (const float*)d_in[25];
    float* out = (float*)d_out;

    float *px, *pqkv, *pbq;
    __nv_bfloat16 *pah, *pal, *poh, *pol, *pf1h, *pf1l, *pf2h, *pf2l;
    __nv_bfloat16 *pwqkvh, *pwqkvl, *pwoh, *pwol, *pw1h, *pw1l, *pw2h, *pw2l, *pw3h, *pw3l, *pwvh, *pwvl;
    cudaGetSymbolAddress((void**)&px,     g_x);
    cudaGetSymbolAddress((void**)&pqkv,   g_qkv);
    cudaGetSymbolAddress((void**)&pbq,    g_bqkv);
    cudaGetSymbolAddress((void**)&pah,    g_ah);
    cudaGetSymbolAddress((void**)&pal,    g_al);
    cudaGetSymbolAddress((void**)&poh,    g_oh);
    cudaGetSymbolAddress((void**)&pol,    g_ol);
    cudaGetSymbolAddress((void**)&pf1h,   g_f1h);
    cudaGetSymbolAddress((void**)&pf1l,   g_f1l);
    cudaGetSymbolAddress((void**)&pf2h,   g_f2h);
    cudaGetSymbolAddress((void**)&pf2l,   g_f2l);
    cudaGetSymbolAddress((void**)&pwqkvh, g_wqkvh);
    cudaGetSymbolAddress((void**)&pwqkvl, g_wqkvl);
    cudaGetSymbolAddress((void**)&pwoh,   g_woh);
    cudaGetSymbolAddress((void**)&pwol,   g_wol);
    cudaGetSymbolAddress((void**)&pw1h,   g_w1h);
    cudaGetSymbolAddress((void**)&pw1l,   g_w1l);
    cudaGetSymbolAddress((void**)&pw2h,   g_w2h);
    cudaGetSymbolAddress((void**)&pw2l,   g_w2l);
    cudaGetSymbolAddress((void**)&pw3h,   g_w3h);
    cudaGetSymbolAddress((void**)&pw3l,   g_w3l);
    cudaGetSymbolAddress((void**)&pwvh,   g_wvh);
    cudaGetSymbolAddress((void**)&pwvl,   g_wvl);

    dim3 tb(32, 8);
    // ---- weight prep ----
    tsplit_qkv_k<<<dim3(24, 2, LL * HH), tb>>>(Wq, pwqkvh, pwqkvl, 0);
    tsplit_qkv_k<<<dim3(24, 2, LL * HH), tb>>>(Wk, pwqkvh, pwqkvl, DD);
    tsplit_qkv_k<<<dim3(24, 2, LL * HH), tb>>>(Wv, pwqkvh, pwqkvl, 2 * DD);
    tsplit_k<<<dim3(DD / 32,  DD / 32,  LL), tb>>>(Wo, pwoh, pwol, DD, DD);
    tsplit_k<<<dim3(DD / 32,  F1N / 32, LL), tb>>>(W1, pw1h, pw1l, DD, F1N);
    tsplit_k<<<dim3(F1N / 32, F2N / 32, LL), tb>>>(W2, pw2h, pw2l, F1N, F2N);
    tsplit_k<<<dim3(F2N / 32, DD / 32,  LL), tb>>>(W3, pw3h, pw3l, F2N, DD);
    split_k<<<(VV * DD + 255) / 256, 256>>>(tok, pwvh, pwvl, VV * DD);
    prep_b_k<<<(LL * D3 + 255) / 256, 256>>>(bq, bk, bv);
    embed_k<<<(MR * DD + 255) / 256, 256>>>(idx, tok, pos);

    for (int l = 0; l < LL; l++) {
        ln_k<<<MR, 256>>>(px, ln1g + l * DD, ln1b + l * DD, pah, pal);
        // QKV: [4096,768] x [2304,768]^T
        mma_gemm<<<dim3(D3 / 128, MR / 128), 256>>>(
            pah, pal, pwqkvh + (size_t)l * D3 * DD, pwqkvl + (size_t)l * D3 * DD,
            pbq + l * D3, nullptr, nullptr, pqkv, nullptr, nullptr, MR, D3, DD, 0);
        scores2_k<<<dim3(SS / 128, SS / 128, BB * HH), 256>>>();
        softmax_k<<<BB * HH * SS, 256>>>();
        av2_k<<<dim3(SS / 128, BB * HH), 256>>>();
        // x += att_scale * (o @ Wo + bo)
        mma_gemm<<<dim3(DD / 128, MR / 128), 256>>>(
            poh, pol, pwoh + (size_t)l * DD * DD, pwol + (size_t)l * DD * DD,
            bo + l * DD, px, att_sc + l, px, nullptr, nullptr, MR, DD, DD, 1);
        ln_k<<<MR, 256>>>(px, ln2g + l * DD, ln2b + l * DD, pah, pal);
        mma_gemm<<<dim3(F1N / 128, MR / 128), 256>>>(
            pah, pal, pw1h + (size_t)l * F1N * DD, pw1l + (size_t)l * F1N * DD,
            b1 + l * F1N, nullptr, nullptr, nullptr, pf1h, pf1l, MR, F1N, DD, 2);
        mma_gemm<<<dim3(F2N / 128, MR / 128), 256>>>(
            pf1h, pf1l, pw2h + (size_t)l * F2N * F1N, pw2l + (size_t)l * F2N * F1N,
            b2 + l * F2N, nullptr, nullptr, nullptr, pf2h, pf2l, MR, F2N, F1N, 2);
        mma_gemm<<<dim3(DD / 128, MR / 128), 256>>>(
            pf2h, pf2l, pw3h + (size_t)l * DD * F2N, pw3l + (size_t)l * DD * F2N,
            b3 + l * DD, px, ffd_sc + l, px, nullptr, nullptr, MR, DD, F2N, 1);
    }

    ln_k<<<MR, 256>>>(px, lnfg, lnfb, pah, pal);
    mma_gemm<<<dim3(VV / 128, MR / 128), 256>>>(
        pah, pal, pwvh, pwvl, nullptr, nullptr, nullptr, out, nullptr, nullptr, MR, VV, DD, 0);
    rowloss_k<<<MR, 256>>>(out, targets);
    if ((long long)out_size > (long long)MR * VV)
        lossreduce_k<<<1, 256>>>(out + (size_t)MR * VV);
}

// round 8
// speedup vs baseline: 2.2157x; 1.0860x over previous
#include <cuda_runtime.h>
#include <cuda_bf16.h>
#include <stdint.h>
#include <stddef.h>
#include <math.h>

// ---------------- problem constants ----------------
#define BB   4
#define SS   1024
#define DD   768
#define LL   12
#define HH   12
#define HS   64
#define VV   32000
#define MR   (BB*SS)        // 4096 rows
#define D3   (3*DD)         // 2304 (qkv concat)
#define F1N  (4*DD)         // 3072
#define F2N  (3*DD)         // 2304

// ---------------- scratch (static device allocs) ----------------
__device__ float g_x   [MR*DD];                 // residual stream fp32
__device__ __nv_bfloat16 g_ah[MR*DD];           // ln output split hi
__device__ __nv_bfloat16 g_al[MR*DD];           // ln output split lo
__device__ float g_att [(size_t)BB*HH*SS*SS];   // fp32 scores, 201 MB
// attention operands, per-head [bh][s][e] bf16 hi/lo
__device__ __nv_bfloat16 g_qh[BB*HH*SS*HS];
__device__ __nv_bfloat16 g_ql[BB*HH*SS*HS];
__device__ __nv_bfloat16 g_kh[BB*HH*SS*HS];
__device__ __nv_bfloat16 g_kl[BB*HH*SS*HS];
__device__ __nv_bfloat16 g_vh[BB*HH*SS*HS];
__device__ __nv_bfloat16 g_vl[BB*HH*SS*HS];
// softmax probabilities, [bh][s][t] bf16 hi/lo
__device__ __nv_bfloat16 g_ph[(size_t)BB*HH*SS*SS];
__device__ __nv_bfloat16 g_pl[(size_t)BB*HH*SS*SS];
__device__ __nv_bfloat16 g_oh[MR*DD];
__device__ __nv_bfloat16 g_ol[MR*DD];
__device__ __nv_bfloat16 g_f1h[(size_t)MR*F1N];
__device__ __nv_bfloat16 g_f1l[(size_t)MR*F1N];
__device__ __nv_bfloat16 g_f2h[(size_t)MR*F2N];
__device__ __nv_bfloat16 g_f2l[(size_t)MR*F2N];
// weights, transposed to [N,K], split bf16 hi/lo
__device__ __nv_bfloat16 g_wqkvh[(size_t)LL*D3*DD];
__device__ __nv_bfloat16 g_wqkvl[(size_t)LL*D3*DD];
__device__ __nv_bfloat16 g_woh[(size_t)LL*DD*DD];
__device__ __nv_bfloat16 g_wol[(size_t)LL*DD*DD];
__device__ __nv_bfloat16 g_w1h[(size_t)LL*F1N*DD];
__device__ __nv_bfloat16 g_w1l[(size_t)LL*F1N*DD];
__device__ __nv_bfloat16 g_w2h[(size_t)LL*F2N*F1N];
__device__ __nv_bfloat16 g_w2l[(size_t)LL*F2N*F1N];
__device__ __nv_bfloat16 g_w3h[(size_t)LL*DD*F2N];
__device__ __nv_bfloat16 g_w3l[(size_t)LL*DD*F2N];
__device__ __nv_bfloat16 g_wvh[(size_t)VV*DD];   // tok_emb (already [N,K])
__device__ __nv_bfloat16 g_wvl[(size_t)VV*DD];
__device__ float g_bqkv[LL*D3];
__device__ float g_rowloss[MR];

// ================= PTX helpers (sm_100 base target safe) =================
__device__ __forceinline__ uint32_t smem_u32(const void* p) {
    uint32_t a;
    asm("{ .reg .u64 t; cvta.to.shared.u64 t, %1; cvt.u32.u64 %0, t; }" : "=r"(a) : "l"(p));
    return a;
}
__device__ __forceinline__ void cp16(uint32_t d, const void* s) {
    asm volatile("cp.async.cg.shared.global [%0], [%1], 16;" :: "r"(d), "l"(s));
}
#define CP_COMMIT() asm volatile("cp.async.commit_group;" ::: "memory")
#define CP_WAIT(n)  asm volatile("cp.async.wait_group %0;" :: "n"(n) : "memory")

__device__ __forceinline__ void ldsm4(uint32_t* r, uint32_t addr) {
    asm volatile("ldmatrix.sync.aligned.m8n8.x4.shared.b16 {%0,%1,%2,%3}, [%4];"
                 : "=r"(r[0]), "=r"(r[1]), "=r"(r[2]), "=r"(r[3]) : "r"(addr));
}
__device__ __forceinline__ void ldsm4t(uint32_t* r, uint32_t addr) {
    asm volatile("ldmatrix.sync.aligned.m8n8.x4.trans.shared.b16 {%0,%1,%2,%3}, [%4];"
                 : "=r"(r[0]), "=r"(r[1]), "=r"(r[2]), "=r"(r[3]) : "r"(addr));
}

// D = A(16x16 row) * B(16x8 col) + D, bf16 in, fp32 out
__device__ __forceinline__ void mma16816(float* c, const uint32_t* a, uint32_t b0, uint32_t b1) {
    asm volatile(
        "mma.sync.aligned.m16n8k16.row.col.f32.bf16.bf16.f32 "
        "{%0,%1,%2,%3}, {%4,%5,%6,%7}, {%8,%9}, {%0,%1,%2,%3};"
        : "+f"(c[0]), "+f"(c[1]), "+f"(c[2]), "+f"(c[3])
        : "r"(a[0]), "r"(a[1]), "r"(a[2]), "r"(a[3]), "r"(b0), "r"(b1));
}

// ---------------- block reductions (deterministic) ----------------
__device__ __forceinline__ float blockSum256(float v, float* sm) {
    #pragma unroll
    for (int o = 16; o > 0; o >>= 1) v += __shfl_down_sync(0xffffffffu, v, o);
    int lane = threadIdx.x & 31, w = threadIdx.x >> 5;
    if (lane == 0) sm[w] = v;
    __syncthreads();
    if (threadIdx.x < 32) {
        v = (lane < 8) ? sm[lane] : 0.0f;
        #pragma unroll
        for (int o = 4; o > 0; o >>= 1) v += __shfl_down_sync(0xffffffffu, v, o);
        if (lane == 0) sm[0] = v;
    }
    __syncthreads();
    float r = sm[0];
    __syncthreads();
    return r;
}
__device__ __forceinline__ float blockMax256(float v, float* sm) {
    #pragma unroll
    for (int o = 16; o > 0; o >>= 1) v = fmaxf(v, __shfl_down_sync(0xffffffffu, v, o));
    int lane = threadIdx.x & 31, w = threadIdx.x >> 5;
    if (lane == 0) sm[w] = v;
    __syncthreads();
    if (threadIdx.x < 32) {
        v = (lane < 8) ? sm[lane] : -1e30f;
        #pragma unroll
        for (int o = 4; o > 0; o >>= 1) v = fmaxf(v, __shfl_down_sync(0xffffffffu, v, o));
        if (lane == 0) sm[0] = v;
    }
    __syncthreads();
    float r = sm[0];
    __syncthreads();
    return r;
}

// ---------------- weight prep: tiled transpose + bf16 split ----------------
__global__ void __launch_bounds__(256) tsplit_k(const float* __restrict__ src,
                                                __nv_bfloat16* __restrict__ dh,
                                                __nv_bfloat16* __restrict__ dl,
                                                int K, int N) {
    __shared__ float tile[32][33];
    int k0 = blockIdx.x * 32, n0 = blockIdx.y * 32;
    size_t so = (size_t)blockIdx.z * K * N;
    int tx = threadIdx.x, ty = threadIdx.y;   // (32,8)
    #pragma unroll
    for (int r = 0; r < 32; r += 8)
        tile[ty + r][tx] = src[so + (size_t)(k0 + ty + r) * N + n0 + tx];
    __syncthreads();
    #pragma unroll
    for (int r = 0; r < 32; r += 8) {
        float v = tile[tx][ty + r];
        size_t di = so + (size_t)(n0 + ty + r) * K + k0 + tx;
        __nv_bfloat16 h = __float2bfloat16(v);
        dh[di] = h;
        dl[di] = __float2bfloat16(v - __bfloat162float(h));
    }
}

// qkv: src [L*HH][DD][HS]; dst row n = nbase + h*HS + e, col k = d
__global__ void __launch_bounds__(256) tsplit_qkv_k(const float* __restrict__ src,
                                                    __nv_bfloat16* __restrict__ dh,
                                                    __nv_bfloat16* __restrict__ dl,
                                                    int nbase) {
    __shared__ float tile[32][33];
    int l = blockIdx.z / HH, h = blockIdx.z % HH;
    int k0 = blockIdx.x * 32, n0 = blockIdx.y * 32;
    const float* s = src + (size_t)blockIdx.z * DD * HS;
    size_t dbase = (size_t)l * D3 * DD + (size_t)(nbase + h * HS) * DD;
    int tx = threadIdx.x, ty = threadIdx.y;
    #pragma unroll
    for (int r = 0; r < 32; r += 8)
        tile[ty + r][tx] = s[(size_t)(k0 + ty + r) * HS + n0 + tx];
    __syncthreads();
    #pragma unroll
    for (int r = 0; r < 32; r += 8) {
        float v = tile[tx][ty + r];
        size_t di = dbase + (size_t)(n0 + ty + r) * DD + k0 + tx;
        __nv_bfloat16 hi = __float2bfloat16(v);
        dh[di] = hi;
        dl[di] = __float2bfloat16(v - __bfloat162float(hi));
    }
}

__global__ void __launch_bounds__(256) split_k(const float* __restrict__ src,
                                               __nv_bfloat16* __restrict__ dh,
                                               __nv_bfloat16* __restrict__ dl, int n) {
    int i = blockIdx.x * 256 + threadIdx.x;
    if (i >= n) return;
    float v = src[i];
    __nv_bfloat16 h = __float2bfloat16(v);
    dh[i] = h;
    dl[i] = __float2bfloat16(v - __bfloat162float(h));
}

__global__ void __launch_bounds__(256) prep_b_k(const float* __restrict__ bq,
                                                const float* __restrict__ bk,
                                                const float* __restrict__ bv) {
    int i = blockIdx.x * 256 + threadIdx.x;
    if (i >= LL * D3) return;
    int l = i / D3, n = i % D3;
    int which = n / DD;
    int h = (n % DD) / HS;
    int e = n % HS;
    const float* b = (which == 0) ? bq : ((which == 1) ? bk : bv);
    g_bqkv[i] = b[(l * HH + h) * HS + e];
}

// ---------------- embedding ----------------
__global__ void __launch_bounds__(256) embed_k(const int* __restrict__ idx,
                                               const float* __restrict__ tok,
                                               const float* __restrict__ pos) {
    int i = blockIdx.x * 256 + threadIdx.x;
    if (i >= MR * DD) return;
    int m = i / DD, d = i % DD;
    int s = m % SS;
    g_x[i] = tok[(size_t)idx[m] * DD + d] + pos[s * DD + d] * 0.03608439182435161f;
}

// ---------------- layernorm -> split bf16 ----------------
__global__ void __launch_bounds__(256) ln_k(const float* __restrict__ x,
                                            const float* __restrict__ g,
                                            const float* __restrict__ b,
                                            __nv_bfloat16* __restrict__ oh,
                                            __nv_bfloat16* __restrict__ ol) {
    __shared__ float sm[8];
    int r = blockIdx.x, t = threadIdx.x;
    const float* xr = x + (size_t)r * DD;
    float v0 = xr[t], v1 = xr[t + 256], v2 = xr[t + 512];
    float mu = blockSum256(v0 + v1 + v2, sm) * (1.0f / (float)DD);
    float d0 = v0 - mu, d1 = v1 - mu, d2 = v2 - mu;
    float var = blockSum256(d0 * d0 + d1 * d1 + d2 * d2, sm) * (1.0f / (float)DD);
    float rs = rsqrtf(var + 1e-5f);
    size_t ro = (size_t)r * DD;
    #pragma unroll
    for (int p = 0; p < 3; p++) {
        int c = t + p * 256;
        float dv = (p == 0 ? d0 : (p == 1 ? d1 : d2));
        float v = dv * rs * g[c] + b[c];
        __nv_bfloat16 h = __float2bfloat16(v);
        oh[ro + c] = h;
        ol[ro + c] = __float2bfloat16(v - __bfloat162float(h));
    }
}

// ---------------- mma.sync split-bf16 GEMM (ldmatrix fragments) ----------------
// C[M,N] = epi(Ah@Bh^T + Ah@Bl^T + Al@Bh^T + bias)
// mode 0: +bias -> outf ; mode 1: resid + scale*(..+bias) -> outf ;
// mode 2: gelu(..+bias) -> outh/outl ; mode 3: qkv split -> g_qh/.../g_vl
#define ROWB   48
#define TILE_B (128*ROWB)     // 6144
#define STG_B  (4*TILE_B)     // 24576

__device__ __forceinline__ void load_stage16(uint32_t base,
                                             const __nv_bfloat16* __restrict__ Ah,
                                             const __nv_bfloat16* __restrict__ Al,
                                             const __nv_bfloat16* __restrict__ Bh,
                                             const __nv_bfloat16* __restrict__ Bl,
                                             int m0, int n0, int K, int k0, int t) {
    int row = t >> 1, ch = t & 1;                 // 128 rows x 2 chunks of 16B
    uint32_t off = row * ROWB + ch * 16;
    size_t ak = (size_t)(m0 + row) * K + k0 + ch * 8;
    size_t bk = (size_t)(n0 + row) * K + k0 + ch * 8;
    cp16(base + off,              Ah + ak);
    cp16(base + TILE_B + off,     Al + ak);
    cp16(base + 2 * TILE_B + off, Bh + bk);
    cp16(base + 3 * TILE_B + off, Bl + bk);
    CP_COMMIT();
}

__global__ void __launch_bounds__(256) mma_gemm(const __nv_bfloat16* __restrict__ Ah,
                                                const __nv_bfloat16* __restrict__ Al,
                                                const __nv_bfloat16* __restrict__ Bh,
                                                const __nv_bfloat16* __restrict__ Bl,
                                                const float* __restrict__ bias,
                                                const float* __restrict__ resid,
                                                const float* __restrict__ scale_ptr,
                                                float* __restrict__ outf,
                                                __nv_bfloat16* __restrict__ outh,
                                                __nv_bfloat16* __restrict__ outl,
                                                int M, int N, int K, int mode) {
    __shared__ __align__(16) char smbuf[2 * STG_B];   // 49152 B static
    uint32_t sb = smem_u32(smbuf);
    int t = threadIdx.x, lane = t & 31, wid = t >> 5;
    int m0 = blockIdx.y * 128, n0 = blockIdx.x * 128;
    int wm = (wid >> 1) * 32, wn = (wid & 1) * 64;
    int g = lane >> 2, t4 = lane & 3;

    uint32_t lrow = lane & 15;
    uint32_t lcol = (lane >> 4) << 4;   // 0 or 16
    uint32_t aoff = (wm + lrow) * ROWB + lcol;
    uint32_t boff = (wn + lrow) * ROWB + lcol;

    float c[2][8][4];
    #pragma unroll
    for (int mf = 0; mf < 2; ++mf)
        #pragma unroll
        for (int nf = 0; nf < 8; ++nf)
            #pragma unroll
            for (int j = 0; j < 4; ++j) c[mf][nf][j] = 0.0f;

    const int nit = K >> 4;
    load_stage16(sb, Ah, Al, Bh, Bl, m0, n0, K, 0, t);

    for (int it = 0; it < nit; ++it) {
        if (it + 1 < nit) {
            load_stage16(sb + ((it + 1) & 1) * STG_B, Ah, Al, Bh, Bl, m0, n0, K, (it + 1) << 4, t);
            CP_WAIT(1);
        } else {
            CP_WAIT(0);
        }
        __syncthreads();

        uint32_t bufA_h = sb + (it & 1) * STG_B;
        uint32_t bufA_l = bufA_h + TILE_B;
        uint32_t bufB_h = bufA_h + 2 * TILE_B;
        uint32_t bufB_l = bufA_h + 3 * TILE_B;

        uint32_t ah[2][4], al[2][4], bh[4][4], bl[4][4];
        #pragma unroll
        for (int mf = 0; mf < 2; ++mf) {
            ldsm4(ah[mf], bufA_h + aoff + mf * 16 * ROWB);
            ldsm4(al[mf], bufA_l + aoff + mf * 16 * ROWB);
        }
        #pragma unroll
        for (int nb = 0; nb < 4; ++nb) {
            ldsm4(bh[nb], bufB_h + boff + nb * 16 * ROWB);
            ldsm4(bl[nb], bufB_l + boff + nb * 16 * ROWB);
        }

        #pragma unroll
        for (int nb = 0; nb < 4; ++nb) {
            #pragma unroll
            for (int h2 = 0; h2 < 2; ++h2) {
                int nf = nb * 2 + h2;
                uint32_t bh0 = bh[nb][h2], bh1 = bh[nb][h2 + 2];
                uint32_t bl0 = bl[nb][h2], bl1 = bl[nb][h2 + 2];
                #pragma unroll
                for (int mf = 0; mf < 2; ++mf) {
                    mma16816(c[mf][nf], ah[mf], bh0, bh1);
                    mma16816(c[mf][nf], al[mf], bh0, bh1);
                    mma16816(c[mf][nf], ah[mf], bl0, bl1);
                }
            }
        }
        __syncthreads();
    }

    // ---- epilogue ----
    float scale = scale_ptr ? *scale_ptr : 1.0f;
    #pragma unroll
    for (int mf = 0; mf < 2; ++mf) {
        #pragma unroll
        for (int nf = 0; nf < 8; ++nf) {
            int row = m0 + wm + mf * 16 + g;
            int col = n0 + wn + nf * 8 + 2 * t4;
            float b0 = 0.0f, b1 = 0.0f;
            if (bias) { b0 = bias[col]; b1 = bias[col + 1]; }
            #pragma unroll
            for (int half = 0; half < 2; ++half) {
                int r = row + half * 8;
                float v0 = c[mf][nf][half * 2 + 0] + b0;
                float v1 = c[mf][nf][half * 2 + 1] + b1;
                size_t ro = (size_t)r * N + col;
                if (mode == 1) {
                    float2 rs = *(const float2*)(resid + ro);
                    v0 = rs.x + scale * v0;
                    v1 = rs.y + scale * v1;
                    *(float2*)(outf + ro) = make_float2(v0, v1);
                } else if (mode == 2) {
                    v0 = 0.5f * v0 * (1.0f + erff(v0 * 0.70710678118654752f));
                    v1 = 0.5f * v1 * (1.0f + erff(v1 * 0.70710678118654752f));
                    __nv_bfloat162 h2, l2;
                    h2.x = __float2bfloat16(v0);
                    h2.y = __float2bfloat16(v1);
                    l2.x = __float2bfloat16(v0 - __bfloat162float(h2.x));
                    l2.y = __float2bfloat16(v1 - __bfloat162float(h2.y));
                    *(__nv_bfloat162*)(outh + ro) = h2;
                    *(__nv_bfloat162*)(outl + ro) = l2;
                } else if (mode == 3) {
                    int bb2 = r >> 10, ss2 = r & 1023;
                    int which = col / DD, rem = col - which * DD;
                    int hh2 = rem >> 6, ee = rem & 63;
                    size_t qo = ((size_t)(bb2 * HH + hh2) * SS + ss2) * HS + ee;
                    __nv_bfloat162 h2, l2;
                    h2.x = __float2bfloat16(v0);
                    h2.y = __float2bfloat16(v1);
                    l2.x = __float2bfloat16(v0 - __bfloat162float(h2.x));
                    l2.y = __float2bfloat16(v1 - __bfloat162float(h2.y));
                    if (which == 0)      { *(__nv_bfloat162*)(g_qh + qo) = h2; *(__nv_bfloat162*)(g_ql + qo) = l2; }
                    else if (which == 1) { *(__nv_bfloat162*)(g_kh + qo) = h2; *(__nv_bfloat162*)(g_kl + qo) = l2; }
                    else                 { *(__nv_bfloat162*)(g_vh + qo) = h2; *(__nv_bfloat162*)(g_vl + qo) = l2; }
                } else {
                    *(float2*)(outf + ro) = make_float2(v0, v1);
                }
            }
        }
    }
}

// ---------------- attention scores via mma (64x64 tiles, causal skip) ----------------
#define ARS 144    // smem row stride bytes for 64-bf16 rows

__global__ void __launch_bounds__(256) scores_mma() {
    int bh = blockIdx.z;
    int s0 = blockIdx.y * 64, t0 = blockIdx.x * 64;
    if (t0 > s0) return;
    __shared__ __align__(16) char smb[4 * 64 * ARS];   // 36864
    uint32_t sb = smem_u32(smb);
    uint32_t Qh = sb, Ql = sb + 9216, Kh = sb + 18432, Kl = sb + 27648;
    int t = threadIdx.x;
    {
        const __nv_bfloat16* qb  = g_qh + ((size_t)bh * SS + s0) * HS;
        const __nv_bfloat16* qlb = g_ql + ((size_t)bh * SS + s0) * HS;
        const __nv_bfloat16* kb  = g_kh + ((size_t)bh * SS + t0) * HS;
        const __nv_bfloat16* klb = g_kl + ((size_t)bh * SS + t0) * HS;
        #pragma unroll
        for (int p = 0; p < 2; ++p) {
            int q = t + p * 256;
            int row = q >> 3, ch = q & 7;
            uint32_t off = row * ARS + ch * 16;
            cp16(Qh + off, qb  + row * HS + ch * 8);
            cp16(Ql + off, qlb + row * HS + ch * 8);
            cp16(Kh + off, kb  + row * HS + ch * 8);
            cp16(Kl + off, klb + row * HS + ch * 8);
        }
    }
    CP_COMMIT(); CP_WAIT(0);
    __syncthreads();
    int lane = t & 31, wid = t >> 5;
    int wm = (wid >> 2) * 32, wn = (wid & 3) * 16;
    int g = lane >> 2, t4 = lane & 3;
    uint32_t aoff = (wm + (lane & 15)) * ARS + ((lane >> 4) << 4);
    uint32_t boff = (wn + (lane & 15)) * ARS + ((lane >> 4) << 4);
    float c[2][2][4] = {};
    #pragma unroll
    for (int ks = 0; ks < 4; ++ks) {
        uint32_t kb2 = ks * 32;
        uint32_t ah[2][4], al[2][4], bh4[4], bl4[4];
        ldsm4(ah[0], Qh + aoff + kb2);
        ldsm4(ah[1], Qh + aoff + 16 * ARS + kb2);
        ldsm4(al[0], Ql + aoff + kb2);
        ldsm4(al[1], Ql + aoff + 16 * ARS + kb2);
        ldsm4(bh4, Kh + boff + kb2);
        ldsm4(bl4, Kl + boff + kb2);
        #pragma unroll
        for (int nf = 0; nf < 2; ++nf) {
            uint32_t b0h = bh4[nf], b1h = bh4[nf + 2];
            uint32_t b0l = bl4[nf], b1l = bl4[nf + 2];
            #pragma unroll
            for (int mf = 0; mf < 2; ++mf) {
                mma16816(c[mf][nf], ah[mf], b0h, b1h);
                mma16816(c[mf][nf], al[mf], b0h, b1h);
                mma16816(c[mf][nf], ah[mf], b0l, b1l);
            }
        }
    }
    size_t ob = (size_t)bh * SS * SS;
    #pragma unroll
    for (int mf = 0; mf < 2; ++mf)
        #pragma unroll
        for (int nf = 0; nf < 2; ++nf) {
            int col = t0 + wn + nf * 8 + 2 * t4;
            #pragma unroll
            for (int half = 0; half < 2; ++half) {
                int row = s0 + wm + mf * 16 + g + half * 8;
                *(float2*)(g_att + ob + (size_t)row * SS + col) =
                    make_float2(c[mf][nf][half * 2] * 0.125f, c[mf][nf][half * 2 + 1] * 0.125f);
            }
        }
}

// ---------------- causal softmax: fp32 scores -> bf16 hi/lo probs ----------------
__global__ void __launch_bounds__(256) softmax_k() {
    __shared__ float sm[8];
    int row = blockIdx.x;
    int s = row % SS;
    size_t base = (size_t)(row / SS) * SS * SS + (size_t)s * SS;
    const float* p = g_att + base;
    int n = s + 1, t = threadIdx.x;
    int ntile = ((s >> 6) + 1) << 6;          // av reads cols [0, ntile)
    float v[4];
    #pragma unroll
    for (int q = 0; q < 4; ++q) {
        int i = t + q * 256;
        v[q] = (i < n) ? p[i] : -1e30f;
    }
    float mx = fmaxf(fmaxf(v[0], v[1]), fmaxf(v[2], v[3]));
    mx = blockMax256(mx, sm);
    float e[4];
    float sum = 0.0f;
    #pragma unroll
    for (int q = 0; q < 4; ++q) {
        int i = t + q * 256;
        e[q] = (i < n) ? expf(v[q] - mx) : 0.0f;
        sum += e[q];
    }
    sum = blockSum256(sum, sm);
    float inv = 1.0f / sum;
    __nv_bfloat16 z = __float2bfloat16(0.0f);
    #pragma unroll
    for (int q = 0; q < 4; ++q) {
        int i = t + q * 256;
        if (i < n) {
            float val = e[q] * inv;
            __nv_bfloat16 h = __float2bfloat16(val);
            g_ph[base + i] = h;
            g_pl[base + i] = __float2bfloat16(val - __bfloat162float(h));
        } else if (i < ntile) {
            g_ph[base + i] = z;
            g_pl[base + i] = z;
        }
    }
}

// ---------------- AV via mma: o = P @ V -> bf16 split ----------------
__global__ void __launch_bounds__(256) av_mma() {
    int bh = blockIdx.y;
    int s0 = blockIdx.x * 64;
    int b = bh / HH, h = bh % HH;
    __shared__ __align__(16) char smb[4 * 64 * ARS];
    uint32_t sb = smem_u32(smb);
    uint32_t Ph = sb, Pl = sb + 9216, Vh = sb + 18432, Vl = sb + 27648;
    int t = threadIdx.x, lane = t & 31, wid = t >> 5;
    int wm = (wid >> 2) * 32, wn = (wid & 3) * 16;
    int g = lane >> 2, t4 = lane & 3;
    uint32_t aoff  = (wm + (lane & 15)) * ARS + ((lane >> 4) << 4);
    uint32_t boffT = (lane & 15) * ARS + wn * 2 + ((lane >> 4) << 4);
    float c[2][2][4] = {};
    int nchunks = (s0 >> 6) + 1;
    for (int j = 0; j < nchunks; ++j) {
        if (j) __syncthreads();
        {
            const __nv_bfloat16* pb  = g_ph + ((size_t)bh * SS + s0) * SS + j * 64;
            const __nv_bfloat16* plb = g_pl + ((size_t)bh * SS + s0) * SS + j * 64;
            const __nv_bfloat16* vb  = g_vh + ((size_t)bh * SS + j * 64) * HS;
            const __nv_bfloat16* vlb = g_vl + ((size_t)bh * SS + j * 64) * HS;
            #pragma unroll
            for (int p = 0; p < 2; ++p) {
                int q = t + p * 256;
                int row = q >> 3, ch = q & 7;
                uint32_t off = row * ARS + ch * 16;
                cp16(Ph + off, pb  + (size_t)row * SS + ch * 8);
                cp16(Pl + off, plb + (size_t)row * SS + ch * 8);
                cp16(Vh + off, vb  + row * HS + ch * 8);
                cp16(Vl + off, vlb + row * HS + ch * 8);
            }
        }
        CP_COMMIT(); CP_WAIT(0);
        __syncthreads();
        #pragma unroll
        for (int ks = 0; ks < 4; ++ks) {
            uint32_t ah[2][4], al[2][4], vh4[4], vl4[4];
            ldsm4(ah[0], Ph + aoff + ks * 32);
            ldsm4(ah[1], Ph + aoff + 16 * ARS + ks * 32);
            ldsm4(al[0], Pl + aoff + ks * 32);
            ldsm4(al[1], Pl + aoff + 16 * ARS + ks * 32);
            ldsm4t(vh4, Vh + boffT + ks * 16 * ARS);
            ldsm4t(vl4, Vl + boffT + ks * 16 * ARS);
            #pragma unroll
            for (int nf = 0; nf < 2; ++nf) {
                uint32_t b0h = vh4[nf * 2], b1h = vh4[nf * 2 + 1];
                uint32_t b0l = vl4[nf * 2], b1l = vl4[nf * 2 + 1];
                #pragma unroll
                for (int mf = 0; mf < 2; ++mf) {
                    mma16816(c[mf][nf], ah[mf], b0h, b1h);
                    mma16816(c[mf][nf], al[mf], b0h, b1h);
                    mma16816(c[mf][nf], ah[mf], b0l, b1l);
                }
            }
        }
    }
    #pragma unroll
    for (int mf = 0; mf < 2; ++mf)
        #pragma unroll
        for (int nf = 0; nf < 2; ++nf) {
            int col = h * HS + wn + nf * 8 + 2 * t4;
            #pragma unroll
            for (int half = 0; half < 2; ++half) {
                int m = b * SS + s0 + wm + mf * 16 + g + half * 8;
                float v0 = c[mf][nf][half * 2], v1 = c[mf][nf][half * 2 + 1];
                __nv_bfloat162 h2, l2;
                h2.x = __float2bfloat16(v0);
                h2.y = __float2bfloat16(v1);
                l2.x = __float2bfloat16(v0 - __bfloat162float(h2.x));
                l2.y = __float2bfloat16(v1 - __bfloat162float(h2.y));
                *(__nv_bfloat162*)(g_oh + (size_t)m * DD + col) = h2;
                *(__nv_bfloat162*)(g_ol + (size_t)m * DD + col) = l2;
            }
        }
}

// ---------------- loss: single-pass online logsumexp ----------------
__global__ void __launch_bounds__(256) rowloss_k(const float* __restrict__ logits,
                                                 const int* __restrict__ targets) {
    __shared__ float smM[8], smS[8];
    int m = blockIdx.x, t = threadIdx.x;
    const float* p = logits + (size_t)m * VV;
    float mx = -1e30f, s = 0.0f;
    for (int i = t; i < VV; i += 256) {
        float x = p[i];
        if (x <= mx) {
            s += expf(x - mx);
        } else {
            s = s * expf(mx - x) + 1.0f;
            mx = x;
        }
    }
    #pragma unroll
    for (int o = 16; o > 0; o >>= 1) {
        float m2 = __shfl_down_sync(0xffffffffu, mx, o);
        float s2 = __shfl_down_sync(0xffffffffu, s, o);
        float mn = fmaxf(mx, m2);
        s = s * expf(mx - mn) + s2 * expf(m2 - mn);
        mx = mn;
    }
    int lane = t & 31, w = t >> 5;
    if (lane == 0) { smM[w] = mx; smS[w] = s; }
    __syncthreads();
    if (t == 0) {
        float M = smM[0], S = smS[0];
        #pragma unroll
        for (int w2 = 1; w2 < 8; ++w2) {
            float m2 = smM[w2], s2 = smS[w2];
            float mn = fmaxf(M, m2);
            S = S * expf(M - mn) + s2 * expf(m2 - mn);
            M = mn;
        }
        float lt = p[targets[m]];
        g_rowloss[m] = -(lt - M - logf(S));
    }
}

__global__ void __launch_bounds__(256) lossreduce_k(float* __restrict__ out) {
    __shared__ float sm[8];
    float s = 0.0f;
    for (int i = threadIdx.x; i < MR; i += 256) s += g_rowloss[i];
    s = blockSum256(s, sm);
    if (threadIdx.x == 0) out[0] = s / (float)MR;
}

// ---------------- launch ----------------
extern "C" void kernel_launch(void* const* d_in, const int* in_sizes, int n_in,
                              void* d_out, int out_size) {
    const int*   idx     = (const int*)  d_in[0];
    const int*   targets = (const int*)  d_in[1];
    const float* tok     = (const float*)d_in[2];
    const float* pos     = (const float*)d_in[3];
    const float* Wq      = (const float*)d_in[4];
    const float* bq      = (const float*)d_in[5];
    const float* Wk      = (const float*)d_in[6];
    const float* bk      = (const float*)d_in[7];
    const float* Wv      = (const float*)d_in[8];
    const float* bv      = (const float*)d_in[9];
    const float* Wo      = (const float*)d_in[10];
    const float* bo      = (const float*)d_in[11];
    const float* ln1g    = (const float*)d_in[12];
    const float* ln1b    = (const float*)d_in[13];
    const float* ln2g    = (const float*)d_in[14];
    const float* ln2b    = (const float*)d_in[15];
    const float* W1      = (const float*)d_in[16];
    const float* b1      = (const float*)d_in[17];
    const float* W2      = (const float*)d_in[18];
    const float* b2      = (const float*)d_in[19];
    const float* W3      = (const float*)d_in[20];
    const float* b3      = (const float*)d_in[21];
    const float* att_sc  = (const float*)d_in[22];
    const float* ffd_sc  = (const float*)d_in[23];
    const float* lnfg    = (const float*)d_in[24];
    const float* lnfb    = (const float*)d_in[25];
    float* out = (float*)d_out;

    float *px, *pbq;
    __nv_bfloat16 *pah, *pal, *poh, *pol, *pf1h, *pf1l, *pf2h, *pf2l;
    __nv_bfloat16 *pwqkvh, *pwqkvl, *pwoh, *pwol, *pw1h, *pw1l, *pw2h, *pw2l, *pw3h, *pw3l, *pwvh, *pwvl;
    cudaGetSymbolAddress((void**)&px,     g_x);
    cudaGetSymbolAddress((void**)&pbq,    g_bqkv);
    cudaGetSymbolAddress((void**)&pah,    g_ah);
    cudaGetSymbolAddress((void**)&pal,    g_al);
    cudaGetSymbolAddress((void**)&poh,    g_oh);
    cudaGetSymbolAddress((void**)&pol,    g_ol);
    cudaGetSymbolAddress((void**)&pf1h,   g_f1h);
    cudaGetSymbolAddress((void**)&pf1l,   g_f1l);
    cudaGetSymbolAddress((void**)&pf2h,   g_f2h);
    cudaGetSymbolAddress((void**)&pf2l,   g_f2l);
    cudaGetSymbolAddress((void**)&pwqkvh, g_wqkvh);
    cudaGetSymbolAddress((void**)&pwqkvl, g_wqkvl);
    cudaGetSymbolAddress((void**)&pwoh,   g_woh);
    cudaGetSymbolAddress((void**)&pwol,   g_wol);
    cudaGetSymbolAddress((void**)&pw1h,   g_w1h);
    cudaGetSymbolAddress((void**)&pw1l,   g_w1l);
    cudaGetSymbolAddress((void**)&pw2h,   g_w2h);
    cudaGetSymbolAddress((void**)&pw2l,   g_w2l);
    cudaGetSymbolAddress((void**)&pw3h,   g_w3h);
    cudaGetSymbolAddress((void**)&pw3l,   g_w3l);
    cudaGetSymbolAddress((void**)&pwvh,   g_wvh);
    cudaGetSymbolAddress((void**)&pwvl,   g_wvl);

    dim3 tb(32, 8);
    // ---- weight prep ----
    tsplit_qkv_k<<<dim3(24, 2, LL * HH), tb>>>(Wq, pwqkvh, pwqkvl, 0);
    tsplit_qkv_k<<<dim3(24, 2, LL * HH), tb>>>(Wk, pwqkvh, pwqkvl, DD);
    tsplit_qkv_k<<<dim3(24, 2, LL * HH), tb>>>(Wv, pwqkvh, pwqkvl, 2 * DD);
    tsplit_k<<<dim3(DD / 32,  DD / 32,  LL), tb>>>(Wo, pwoh, pwol, DD, DD);
    tsplit_k<<<dim3(DD / 32,  F1N / 32, LL), tb>>>(W1, pw1h, pw1l, DD, F1N);
    tsplit_k<<<dim3(F1N / 32, F2N / 32, LL), tb>>>(W2, pw2h, pw2l, F1N, F2N);
    tsplit_k<<<dim3(F2N / 32, DD / 32,  LL), tb>>>(W3, pw3h, pw3l, F2N, DD);
    split_k<<<(VV * DD + 255) / 256, 256>>>(tok, pwvh, pwvl, VV * DD);
    prep_b_k<<<(LL * D3 + 255) / 256, 256>>>(bq, bk, bv);
    embed_k<<<(MR * DD + 255) / 256, 256>>>(idx, tok, pos);

    for (int l = 0; l < LL; l++) {
        ln_k<<<MR, 256>>>(px, ln1g + l * DD, ln1b + l * DD, pah, pal);
        // QKV: [4096,768] x [2304,768]^T -> split per-head q/k/v buffers
        mma_gemm<<<dim3(D3 / 128, MR / 128), 256>>>(
            pah, pal, pwqkvh + (size_t)l * D3 * DD, pwqkvl + (size_t)l * D3 * DD,
            pbq + l * D3, nullptr, nullptr, nullptr, nullptr, nullptr, MR, D3, DD, 3);
        scores_mma<<<dim3(16, 16, BB * HH), 256>>>();
        softmax_k<<<BB * HH * SS, 256>>>();
        av_mma<<<dim3(16, BB * HH), 256>>>();
        // x += att_scale * (o @ Wo + bo)
        mma_gemm<<<dim3(DD / 128, MR / 128), 256>>>(
            poh, pol, pwoh + (size_t)l * DD * DD, pwol + (size_t)l * DD * DD,
            bo + l * DD, px, att_sc + l, px, nullptr, nullptr, MR, DD, DD, 1);
        ln_k<<<MR, 256>>>(px, ln2g + l * DD, ln2b + l * DD, pah, pal);
        mma_gemm<<<dim3(F1N / 128, MR / 128), 256>>>(
            pah, pal, pw1h + (size_t)l * F1N * DD, pw1l + (size_t)l * F1N * DD,
            b1 + l * F1N, nullptr, nullptr, nullptr, pf1h, pf1l, MR, F1N, DD, 2);
        mma_gemm<<<dim3(F2N / 128, MR / 128), 256>>>(
            pf1h, pf1l, pw2h + (size_t)l * F2N * F1N, pw2l + (size_t)l * F2N * F1N,
            b2 + l * F2N, nullptr, nullptr, nullptr, pf2h, pf2l, MR, F2N, F1N, 2);
        mma_gemm<<<dim3(DD / 128, MR / 128), 256>>>(
            pf2h, pf2l, pw3h + (size_t)l * DD * F2N, pw3l + (size_t)l * DD * F2N,
            b3 + l * DD, px, ffd_sc + l, px, nullptr, nullptr, MR, DD, F2N, 1);
    }

    ln_k<<<MR, 256>>>(px, lnfg, lnfb, pah, pal);
    mma_gemm<<<dim3(VV / 128, MR / 128), 256>>>(
        pah, pal, pwvh, pwvl, nullptr, nullptr, nullptr, out, nullptr, nullptr, MR, VV, DD, 0);
    rowloss_k<<<MR, 256>>>(out, targets);
    if ((long long)out_size > (long long)MR * VV)
        lossreduce_k<<<1, 256>>>(out + (size_t)MR * VV);
}